// round 4
// baseline (speedup 1.0000x reference)
#include <cuda_runtime.h>
#include <cstdint>

// Problem constants (fixed by setup_inputs)
#define MAXN 100000
#define MAXE 3200000
#define FIN  512
#define H1DIM 64   // 8 heads x 8 ch
#define HEADS 8
#define C1 8
#define NCLS 16
#define MAXT (MAXE + MAXN)

// ---------------- scratch (device globals; no allocations allowed) --------
__device__ __align__(16) float g_h1[MAXN * H1DIM];     // x @ W1
__device__ __align__(16) float g_as1[MAXN * HEADS];
__device__ __align__(16) float g_ad1[MAXN * HEADS];
__device__ __align__(16) float g_denom1[MAXN * HEADS];
__device__ __align__(16) float g_out1[MAXN * H1DIM];   // layer1 aggregate (+b1)
__device__ __align__(16) float g_h2[MAXN * NCLS];      // elu(out1) @ W2
__device__ __align__(16) float g_as2[MAXN];
__device__ __align__(16) float g_ad2[MAXN];
__device__ __align__(16) float g_denom2[MAXN];
__device__ __align__(16) int   g_src[MAXT];
__device__ __align__(16) int   g_dst[MAXT];
__device__ int g_is64;

// vectorized L2 reduction (sm_90+)
__device__ __forceinline__ void red_add_v4(float* addr, float a, float b, float c, float d) {
    asm volatile("red.global.add.v4.f32 [%0], {%1, %2, %3, %4};"
                 :: "l"(addr), "f"(a), "f"(b), "f"(c), "f"(d) : "memory");
}

__device__ __forceinline__ float lrelu(float v) { return v > 0.f ? v : 0.2f * v; }

// ---------------- dtype detect: int64 edge_index has zero high words -------
__global__ void detect_kernel(const int* __restrict__ ei32) {
    // lane t inspects the would-be high word of int64 element t
    unsigned ballot = __ballot_sync(0xFFFFFFFF, ei32[2 * threadIdx.x + 1] != 0);
    if (threadIdx.x == 0) g_is64 = (ballot == 0u) ? 1 : 0;
}

// ---------------- convert edges to int32 src/dst, append self-loops --------
__global__ void convert_kernel(const void* __restrict__ ei, int E, int N) {
    int e = blockIdx.x * blockDim.x + threadIdx.x;
    int T = E + N;
    if (e >= T) return;
    if (e >= E) {
        g_src[e] = e - E;
        g_dst[e] = e - E;
        return;
    }
    if (g_is64) {
        const long long* p = (const long long*)ei;
        g_src[e] = (int)p[e];
        g_dst[e] = (int)p[(size_t)E + e];
    } else {
        const int* p = (const int*)ei;
        g_src[e] = p[e];
        g_dst[e] = p[E + e];
    }
}

// ---------------- init: zero denominators, bias-seed outputs --------------
__global__ void init_kernel(const float* __restrict__ b1, const float* __restrict__ b2,
                            float* __restrict__ out, int N) {
    int gid = blockIdx.x * blockDim.x + threadIdx.x;
    if (gid < N * H1DIM) g_out1[gid] = b1[gid & (H1DIM - 1)];
    if (gid < N * NCLS)  out[gid]    = b2[gid & (NCLS - 1)];
    if (gid < N * HEADS) g_denom1[gid] = 0.f;
    if (gid < N)         g_denom2[gid] = 0.f;
}

// ---------------- GEMM1: h1 = x @ W1   (M x 512 @ 512 x 64) ---------------
#define BM 128
#define BN 64
#define BK 16
__global__ __launch_bounds__(256) void gemm1_kernel(const float* __restrict__ x,
                                                    const float* __restrict__ W1, int M) {
    __shared__ float As[BK][BM];
    __shared__ float Bs[BK][BN];
    int tid = threadIdx.x;
    int m0 = blockIdx.x * BM;
    int tx = tid & 15;        // 0..15 -> 4 cols
    int ty = tid >> 4;        // 0..15 -> 8 rows
    float acc[8][4];
#pragma unroll
    for (int i = 0; i < 8; i++)
#pragma unroll
        for (int j = 0; j < 4; j++) acc[i][j] = 0.f;

    for (int k0 = 0; k0 < FIN; k0 += BK) {
        // load A tile (128x16) transposed into As[k][m]
#pragma unroll
        for (int l = 0; l < 2; l++) {
            int idx = tid + l * 256;      // 0..511 float4 slots
            int row = idx >> 2;
            int c4  = idx & 3;
            float4 v = make_float4(0.f, 0.f, 0.f, 0.f);
            int gr = m0 + row;
            if (gr < M) v = *(const float4*)(x + (size_t)gr * FIN + k0 + c4 * 4);
            As[c4 * 4 + 0][row] = v.x;
            As[c4 * 4 + 1][row] = v.y;
            As[c4 * 4 + 2][row] = v.z;
            As[c4 * 4 + 3][row] = v.w;
        }
        // load B tile (16x64)
        {
            int row = tid >> 4;           // 0..15
            int c4  = tid & 15;           // 0..15
            float4 v = *(const float4*)(W1 + (size_t)(k0 + row) * BN + c4 * 4);
            *(float4*)&Bs[row][c4 * 4] = v;
        }
        __syncthreads();
#pragma unroll
        for (int k = 0; k < BK; k++) {
            float4 b  = *(float4*)&Bs[k][tx * 4];
            float4 a0 = *(float4*)&As[k][ty * 8];
            float4 a1 = *(float4*)&As[k][ty * 8 + 4];
            float a[8] = {a0.x, a0.y, a0.z, a0.w, a1.x, a1.y, a1.z, a1.w};
#pragma unroll
            for (int i = 0; i < 8; i++) {
                acc[i][0] += a[i] * b.x;
                acc[i][1] += a[i] * b.y;
                acc[i][2] += a[i] * b.z;
                acc[i][3] += a[i] * b.w;
            }
        }
        __syncthreads();
    }
#pragma unroll
    for (int i = 0; i < 8; i++) {
        int gr = m0 + ty * 8 + i;
        if (gr < M) {
            float4 v = make_float4(acc[i][0], acc[i][1], acc[i][2], acc[i][3]);
            *(float4*)(g_h1 + (size_t)gr * H1DIM + tx * 4) = v;
        }
    }
}

// ---------------- per-node attention coefficients (layer 1) ---------------
__global__ void attn1_kernel(const float* __restrict__ att_src,
                             const float* __restrict__ att_dst, int N) {
    int idx = blockIdx.x * blockDim.x + threadIdx.x;  // n*8 + head
    if (idx >= N * HEADS) return;
    int n = idx >> 3, hh = idx & 7;
    const float* hp = g_h1 + (size_t)n * H1DIM + hh * C1;
    float4 h0 = *(const float4*)hp;
    float4 h1v = *(const float4*)(hp + 4);
    float4 s0 = *(const float4*)(att_src + hh * C1);
    float4 s1 = *(const float4*)(att_src + hh * C1 + 4);
    float4 d0 = *(const float4*)(att_dst + hh * C1);
    float4 d1 = *(const float4*)(att_dst + hh * C1 + 4);
    float as = h0.x * s0.x + h0.y * s0.y + h0.z * s0.z + h0.w * s0.w +
               h1v.x * s1.x + h1v.y * s1.y + h1v.z * s1.z + h1v.w * s1.w;
    float ad = h0.x * d0.x + h0.y * d0.y + h0.z * d0.z + h0.w * d0.w +
               h1v.x * d1.x + h1v.y * d1.y + h1v.z * d1.z + h1v.w * d1.w;
    g_as1[idx] = as;
    g_ad1[idx] = ad;
}

// ---------------- layer 1: softmax denominators ----------------------------
__global__ void edge_denom1(int T) {
    int e = blockIdx.x * blockDim.x + threadIdx.x;
    if (e >= T) return;
    int src = g_src[e], dst = g_dst[e];
    float4 s0 = *(const float4*)(g_as1 + (size_t)src * HEADS);
    float4 s1 = *(const float4*)(g_as1 + (size_t)src * HEADS + 4);
    float4 d0 = *(const float4*)(g_ad1 + (size_t)dst * HEADS);
    float4 d1 = *(const float4*)(g_ad1 + (size_t)dst * HEADS + 4);
    float w0 = expf(lrelu(s0.x + d0.x));
    float w1 = expf(lrelu(s0.y + d0.y));
    float w2 = expf(lrelu(s0.z + d0.z));
    float w3 = expf(lrelu(s0.w + d0.w));
    float w4 = expf(lrelu(s1.x + d1.x));
    float w5 = expf(lrelu(s1.y + d1.y));
    float w6 = expf(lrelu(s1.z + d1.z));
    float w7 = expf(lrelu(s1.w + d1.w));
    red_add_v4(g_denom1 + (size_t)dst * HEADS, w0, w1, w2, w3);
    red_add_v4(g_denom1 + (size_t)dst * HEADS + 4, w4, w5, w6, w7);
}

// ---------------- layer 1: weighted aggregation (16 thr/edge) -------------
__global__ void edge_agg1(int T) {
    int gid = blockIdx.x * blockDim.x + threadIdx.x;
    int e = gid >> 4;
    int t = gid & 15;           // t*4 = channel offset; head = t/2
    if (e >= T) return;
    int src = g_src[e], dst = g_dst[e];
    int head = t >> 1;
    float as = g_as1[(size_t)src * HEADS + head];
    float ad = g_ad1[(size_t)dst * HEADS + head];
    float w = expf(lrelu(as + ad));
    float alpha = w / g_denom1[(size_t)dst * HEADS + head];
    float4 hv = *(const float4*)(g_h1 + (size_t)src * H1DIM + t * 4);
    red_add_v4(g_out1 + (size_t)dst * H1DIM + t * 4,
               hv.x * alpha, hv.y * alpha, hv.z * alpha, hv.w * alpha);
}

// ---------------- GEMM2 (+elu on input) + attention coeffs (layer 2) ------
__global__ __launch_bounds__(256) void gemm2_kernel(const float* __restrict__ W2,
                                                    const float* __restrict__ att_src2,
                                                    const float* __restrict__ att_dst2, int N) {
    __shared__ float W2s[H1DIM * NCLS];
    __shared__ float s2[NCLS], d2[NCLS];
    int tid = threadIdx.x;
    for (int i = tid; i < H1DIM * NCLS; i += 256) W2s[i] = W2[i];
    if (tid < NCLS) { s2[tid] = att_src2[tid]; d2[tid] = att_dst2[tid]; }
    __syncthreads();
    int n = blockIdx.x * blockDim.x + tid;
    if (n >= N) return;
    float acc[NCLS];
#pragma unroll
    for (int j = 0; j < NCLS; j++) acc[j] = 0.f;
    const float* row = g_out1 + (size_t)n * H1DIM;
#pragma unroll
    for (int c4 = 0; c4 < H1DIM / 4; c4++) {
        float4 v = *(const float4*)(row + c4 * 4);
        float vv[4] = {v.x, v.y, v.z, v.w};
#pragma unroll
        for (int u = 0; u < 4; u++) {
            float val = vv[u];
            val = val > 0.f ? val : (expf(val) - 1.f);   // elu
            int c = c4 * 4 + u;
#pragma unroll
            for (int j = 0; j < NCLS; j++) acc[j] += val * W2s[c * NCLS + j];
        }
    }
    float as = 0.f, ad = 0.f;
#pragma unroll
    for (int j = 0; j < NCLS; j++) { as += acc[j] * s2[j]; ad += acc[j] * d2[j]; }
    float* hp = g_h2 + (size_t)n * NCLS;
#pragma unroll
    for (int j4 = 0; j4 < NCLS / 4; j4++) {
        *(float4*)(hp + j4 * 4) = make_float4(acc[j4 * 4], acc[j4 * 4 + 1],
                                              acc[j4 * 4 + 2], acc[j4 * 4 + 3]);
    }
    g_as2[n] = as;
    g_ad2[n] = ad;
}

// ---------------- layer 2: softmax denominators ----------------------------
__global__ void edge_denom2(int T) {
    int e = blockIdx.x * blockDim.x + threadIdx.x;
    if (e >= T) return;
    int src = g_src[e], dst = g_dst[e];
    float w = expf(lrelu(g_as2[src] + g_ad2[dst]));
    atomicAdd(g_denom2 + dst, w);
}

// ---------------- layer 2: weighted aggregation (4 thr/edge) --------------
__global__ void edge_agg2(int T, float* __restrict__ out) {
    int gid = blockIdx.x * blockDim.x + threadIdx.x;
    int e = gid >> 2;
    int t = gid & 3;
    if (e >= T) return;
    int src = g_src[e], dst = g_dst[e];
    float w = expf(lrelu(g_as2[src] + g_ad2[dst]));
    float alpha = w / g_denom2[dst];
    float4 hv = *(const float4*)(g_h2 + (size_t)src * NCLS + t * 4);
    red_add_v4(out + (size_t)dst * NCLS + t * 4,
               hv.x * alpha, hv.y * alpha, hv.z * alpha, hv.w * alpha);
}

// ---------------------------------------------------------------------------
extern "C" void kernel_launch(void* const* d_in, const int* in_sizes, int n_in,
                              void* d_out, int out_size) {
    const float* x        = (const float*)d_in[0];
    const void*  ei       = d_in[1];
    const float* W1       = (const float*)d_in[2];
    const float* att_src1 = (const float*)d_in[3];
    const float* att_dst1 = (const float*)d_in[4];
    const float* b1       = (const float*)d_in[5];
    const float* W2       = (const float*)d_in[6];
    const float* att_src2 = (const float*)d_in[7];
    const float* att_dst2 = (const float*)d_in[8];
    const float* b2       = (const float*)d_in[9];
    float* out = (float*)d_out;

    int N = in_sizes[0] / FIN;       // 100000
    int E = in_sizes[1] / 2;         // 3200000
    int T = E + N;                   // edges incl. self-loops

    detect_kernel<<<1, 32>>>((const int*)ei);
    convert_kernel<<<(T + 255) / 256, 256>>>(ei, E, N);
    init_kernel<<<(N * H1DIM + 255) / 256, 256>>>(b1, b2, out, N);
    gemm1_kernel<<<(N + BM - 1) / BM, 256>>>(x, W1, N);
    attn1_kernel<<<(N * HEADS + 255) / 256, 256>>>(att_src1, att_dst1, N);
    edge_denom1<<<(T + 255) / 256, 256>>>(T);
    edge_agg1<<<((long long)T * 16 + 255) / 256, 256>>>(T);
    gemm2_kernel<<<(N + 255) / 256, 256>>>(W2, att_src2, att_dst2, N);
    edge_denom2<<<(T + 255) / 256, 256>>>(T);
    edge_agg2<<<((long long)T * 4 + 255) / 256, 256>>>(T, out);
}

// round 5
// speedup vs baseline: 1.1044x; 1.1044x over previous
#include <cuda_runtime.h>
#include <cstdint>

// Problem constants (fixed by setup_inputs)
#define MAXN 100000
#define MAXE 3200000
#define FIN  512
#define H1DIM 64   // 8 heads x 8 ch
#define HEADS 8
#define C1 8
#define NCLS 16
#define MAXT (MAXE + MAXN)

// ---------------- scratch (device globals; no allocations allowed) --------
__device__ __align__(16) float g_h1[MAXN * H1DIM];     // x @ W1
__device__ __align__(16) float g_as1[MAXN * HEADS];
__device__ __align__(16) float g_ad1[MAXN * HEADS];
__device__ __align__(16) float g_denom1[MAXN * HEADS];
__device__ __align__(16) float g_out1[MAXN * H1DIM];   // layer1 unnormalized acc
__device__ __align__(16) float g_h2[MAXN * NCLS];      // elu(norm(out1)) @ W2
__device__ __align__(16) float g_as2[MAXN];
__device__ __align__(16) float g_ad2[MAXN];
__device__ __align__(16) float g_denom2[MAXN];
__device__ __align__(16) int   g_src[MAXT];
__device__ __align__(16) int   g_dst[MAXT];
__device__ int g_is64;

// vectorized L2 reduction (sm_90+)
__device__ __forceinline__ void red_add_v4(float* addr, float a, float b, float c, float d) {
    asm volatile("red.global.add.v4.f32 [%0], {%1, %2, %3, %4};"
                 :: "l"(addr), "f"(a), "f"(b), "f"(c), "f"(d) : "memory");
}
__device__ __forceinline__ void red_add_f32(float* addr, float a) {
    asm volatile("red.global.add.f32 [%0], %1;" :: "l"(addr), "f"(a) : "memory");
}

__device__ __forceinline__ float lrelu(float v) { return v > 0.f ? v : 0.2f * v; }

// ---------------- dtype detect: int64 edge_index has zero high words -------
__global__ void detect_kernel(const int* __restrict__ ei32) {
    unsigned ballot = __ballot_sync(0xFFFFFFFF, ei32[2 * threadIdx.x + 1] != 0);
    if (threadIdx.x == 0) g_is64 = (ballot == 0u) ? 1 : 0;
}

// ---------------- convert edges to int32 src/dst, append self-loops --------
__global__ void convert_kernel(const void* __restrict__ ei, int E, int N) {
    int e = blockIdx.x * blockDim.x + threadIdx.x;
    int T = E + N;
    if (e >= T) return;
    if (e >= E) {
        g_src[e] = e - E;
        g_dst[e] = e - E;
        return;
    }
    if (g_is64) {
        const long long* p = (const long long*)ei;
        g_src[e] = (int)p[e];
        g_dst[e] = (int)p[(size_t)E + e];
    } else {
        const int* p = (const int*)ei;
        g_src[e] = p[e];
        g_dst[e] = p[E + e];
    }
}

// ---------------- init: zero all accumulators ------------------------------
__global__ void init_kernel(float* __restrict__ out, int N) {
    int gid = blockIdx.x * blockDim.x + threadIdx.x;
    if (gid < N * H1DIM) g_out1[gid] = 0.f;
    if (gid < N * NCLS)  out[gid]    = 0.f;
    if (gid < N * HEADS) g_denom1[gid] = 0.f;
    if (gid < N)         g_denom2[gid] = 0.f;
}

// ---------------- GEMM1: h1 = x @ W1   (M x 512 @ 512 x 64) ---------------
// 128 threads, 8x8 micro-tile per thread: 64 FFMA per 4 LDS.128
#define BM 128
#define BMP (BM + 4)   // pad: breaks 4-way STS bank conflict, keeps 16B align
#define BN 64
#define BK 16
__global__ __launch_bounds__(128) void gemm1_kernel(const float* __restrict__ x,
                                                    const float* __restrict__ W1, int M) {
    __shared__ float As[BK][BMP];
    __shared__ float Bs[BK][BN];
    int tid = threadIdx.x;
    int m0 = blockIdx.x * BM;
    int tx = tid & 7;         // 0..7  -> 8 cols each
    int ty = tid >> 3;        // 0..15 -> 8 rows each
    float acc[8][8];
#pragma unroll
    for (int i = 0; i < 8; i++)
#pragma unroll
        for (int j = 0; j < 8; j++) acc[i][j] = 0.f;

    for (int k0 = 0; k0 < FIN; k0 += BK) {
        // A tile (128x16) transposed into As[k][m]: 512 float4 slots, 4/thread
#pragma unroll
        for (int l = 0; l < 4; l++) {
            int idx = tid + l * 128;
            int row = idx >> 2;
            int c4  = idx & 3;
            float4 v = make_float4(0.f, 0.f, 0.f, 0.f);
            int gr = m0 + row;
            if (gr < M) v = *(const float4*)(x + (size_t)gr * FIN + k0 + c4 * 4);
            As[c4 * 4 + 0][row] = v.x;
            As[c4 * 4 + 1][row] = v.y;
            As[c4 * 4 + 2][row] = v.z;
            As[c4 * 4 + 3][row] = v.w;
        }
        // B tile (16x64): 256 float4 slots, 2/thread
#pragma unroll
        for (int l = 0; l < 2; l++) {
            int idx = tid + l * 128;
            int row = idx >> 4;
            int c4  = idx & 15;
            *(float4*)&Bs[row][c4 * 4] = *(const float4*)(W1 + (size_t)(k0 + row) * BN + c4 * 4);
        }
        __syncthreads();
#pragma unroll
        for (int k = 0; k < BK; k++) {
            float4 b0 = *(float4*)&Bs[k][tx * 8];
            float4 b1 = *(float4*)&Bs[k][tx * 8 + 4];
            float4 a0 = *(float4*)&As[k][ty * 8];
            float4 a1 = *(float4*)&As[k][ty * 8 + 4];
            float a[8] = {a0.x, a0.y, a0.z, a0.w, a1.x, a1.y, a1.z, a1.w};
            float b[8] = {b0.x, b0.y, b0.z, b0.w, b1.x, b1.y, b1.z, b1.w};
#pragma unroll
            for (int i = 0; i < 8; i++)
#pragma unroll
                for (int j = 0; j < 8; j++) acc[i][j] += a[i] * b[j];
        }
        __syncthreads();
    }
#pragma unroll
    for (int i = 0; i < 8; i++) {
        int gr = m0 + ty * 8 + i;
        if (gr < M) {
            float* op = g_h1 + (size_t)gr * H1DIM + tx * 8;
            *(float4*)op = make_float4(acc[i][0], acc[i][1], acc[i][2], acc[i][3]);
            *(float4*)(op + 4) = make_float4(acc[i][4], acc[i][5], acc[i][6], acc[i][7]);
        }
    }
}

// ---------------- per-node attention coefficients (layer 1) ---------------
__global__ void attn1_kernel(const float* __restrict__ att_src,
                             const float* __restrict__ att_dst, int N) {
    int idx = blockIdx.x * blockDim.x + threadIdx.x;  // n*8 + head
    if (idx >= N * HEADS) return;
    int n = idx >> 3, hh = idx & 7;
    const float* hp = g_h1 + (size_t)n * H1DIM + hh * C1;
    float4 h0 = *(const float4*)hp;
    float4 h1v = *(const float4*)(hp + 4);
    float4 s0 = *(const float4*)(att_src + hh * C1);
    float4 s1 = *(const float4*)(att_src + hh * C1 + 4);
    float4 d0 = *(const float4*)(att_dst + hh * C1);
    float4 d1 = *(const float4*)(att_dst + hh * C1 + 4);
    float as = h0.x * s0.x + h0.y * s0.y + h0.z * s0.z + h0.w * s0.w +
               h1v.x * s1.x + h1v.y * s1.y + h1v.z * s1.z + h1v.w * s1.w;
    float ad = h0.x * d0.x + h0.y * d0.y + h0.z * d0.z + h0.w * d0.w +
               h1v.x * d1.x + h1v.y * d1.y + h1v.z * d1.z + h1v.w * d1.w;
    g_as1[idx] = as;
    g_ad1[idx] = ad;
}

// ---------------- layer 1 fused: unnormalized agg + denom (8 thr/edge) ----
__global__ void edge_agg1(int T) {
    int gid = blockIdx.x * blockDim.x + threadIdx.x;
    int e = gid >> 3;
    int h = gid & 7;            // head; 8 channels each
    if (e >= T) return;
    int src = g_src[e], dst = g_dst[e];
    float w = __expf(lrelu(g_as1[(size_t)src * HEADS + h] + g_ad1[(size_t)dst * HEADS + h]));
    const float* hp = g_h1 + (size_t)src * H1DIM + h * 8;
    float4 v0 = *(const float4*)hp;
    float4 v1 = *(const float4*)(hp + 4);
    float* op = g_out1 + (size_t)dst * H1DIM + h * 8;
    red_add_v4(op, v0.x * w, v0.y * w, v0.z * w, v0.w * w);
    red_add_v4(op + 4, v1.x * w, v1.y * w, v1.z * w, v1.w * w);
    red_add_f32(g_denom1 + (size_t)dst * HEADS + h, w);
}

// ---------------- GEMM2: normalize1 + bias + elu fused on input -----------
__global__ __launch_bounds__(256) void gemm2_kernel(const float* __restrict__ W2,
                                                    const float* __restrict__ att_src2,
                                                    const float* __restrict__ att_dst2,
                                                    const float* __restrict__ b1, int N) {
    __shared__ float W2s[H1DIM * NCLS];
    __shared__ float s2[NCLS], d2[NCLS], b1s[H1DIM];
    int tid = threadIdx.x;
    for (int i = tid; i < H1DIM * NCLS; i += 256) W2s[i] = W2[i];
    if (tid < NCLS) { s2[tid] = att_src2[tid]; d2[tid] = att_dst2[tid]; }
    if (tid < H1DIM) b1s[tid] = b1[tid];
    __syncthreads();
    int n = blockIdx.x * blockDim.x + tid;
    if (n >= N) return;
    float4 dn0 = *(const float4*)(g_denom1 + (size_t)n * HEADS);
    float4 dn1 = *(const float4*)(g_denom1 + (size_t)n * HEADS + 4);
    float inv[8] = {1.f / dn0.x, 1.f / dn0.y, 1.f / dn0.z, 1.f / dn0.w,
                    1.f / dn1.x, 1.f / dn1.y, 1.f / dn1.z, 1.f / dn1.w};
    float acc[NCLS];
#pragma unroll
    for (int j = 0; j < NCLS; j++) acc[j] = 0.f;
    const float* row = g_out1 + (size_t)n * H1DIM;
#pragma unroll
    for (int c4 = 0; c4 < H1DIM / 4; c4++) {
        float4 v = *(const float4*)(row + c4 * 4);
        float vv[4] = {v.x, v.y, v.z, v.w};
#pragma unroll
        for (int u = 0; u < 4; u++) {
            int c = c4 * 4 + u;
            float val = vv[u] * inv[c >> 3] + b1s[c];      // normalize + bias
            val = val > 0.f ? val : (__expf(val) - 1.f);   // elu
#pragma unroll
            for (int j = 0; j < NCLS; j++) acc[j] += val * W2s[c * NCLS + j];
        }
    }
    float as = 0.f, ad = 0.f;
#pragma unroll
    for (int j = 0; j < NCLS; j++) { as += acc[j] * s2[j]; ad += acc[j] * d2[j]; }
    float* hp = g_h2 + (size_t)n * NCLS;
#pragma unroll
    for (int j4 = 0; j4 < NCLS / 4; j4++) {
        *(float4*)(hp + j4 * 4) = make_float4(acc[j4 * 4], acc[j4 * 4 + 1],
                                              acc[j4 * 4 + 2], acc[j4 * 4 + 3]);
    }
    g_as2[n] = as;
    g_ad2[n] = ad;
}

// ---------------- layer 2 fused: unnormalized agg + denom (4 thr/edge) ----
__global__ void edge_agg2(int T, float* __restrict__ out) {
    int gid = blockIdx.x * blockDim.x + threadIdx.x;
    int e = gid >> 2;
    int t = gid & 3;
    if (e >= T) return;
    int src = g_src[e], dst = g_dst[e];
    float w = __expf(lrelu(g_as2[src] + g_ad2[dst]));
    float4 hv = *(const float4*)(g_h2 + (size_t)src * NCLS + t * 4);
    red_add_v4(out + (size_t)dst * NCLS + t * 4,
               hv.x * w, hv.y * w, hv.z * w, hv.w * w);
    if (t == 0) red_add_f32(g_denom2 + dst, w);
}

// ---------------- layer 2: normalize + bias (in-place on out) -------------
__global__ void norm2_kernel(float* __restrict__ out, const float* __restrict__ b2, int N) {
    int gid = blockIdx.x * blockDim.x + threadIdx.x;
    if (gid >= N * NCLS) return;
    int n = gid >> 4, j = gid & 15;
    out[gid] = out[gid] / g_denom2[n] + b2[j];
}

// ---------------------------------------------------------------------------
extern "C" void kernel_launch(void* const* d_in, const int* in_sizes, int n_in,
                              void* d_out, int out_size) {
    const float* x        = (const float*)d_in[0];
    const void*  ei       = d_in[1];
    const float* W1       = (const float*)d_in[2];
    const float* att_src1 = (const float*)d_in[3];
    const float* att_dst1 = (const float*)d_in[4];
    const float* b1       = (const float*)d_in[5];
    const float* W2       = (const float*)d_in[6];
    const float* att_src2 = (const float*)d_in[7];
    const float* att_dst2 = (const float*)d_in[8];
    const float* b2       = (const float*)d_in[9];
    float* out = (float*)d_out;

    int N = in_sizes[0] / FIN;       // 100000
    int E = in_sizes[1] / 2;         // 3200000
    int T = E + N;                   // edges incl. self-loops

    detect_kernel<<<1, 32>>>((const int*)ei);
    convert_kernel<<<(T + 255) / 256, 256>>>(ei, E, N);
    init_kernel<<<(N * H1DIM + 255) / 256, 256>>>(out, N);
    gemm1_kernel<<<(N + BM - 1) / BM, 128>>>(x, W1, N);
    attn1_kernel<<<(N * HEADS + 255) / 256, 256>>>(att_src1, att_dst1, N);
    edge_agg1<<<((long long)T * 8 + 255) / 256, 256>>>(T);
    gemm2_kernel<<<(N + 255) / 256, 256>>>(W2, att_src2, att_dst2, b1, N);
    edge_agg2<<<((long long)T * 4 + 255) / 256, 256>>>(T, out);
    norm2_kernel<<<(N * NCLS + 255) / 256, 256>>>(out, b2, N);
}

// round 6
// speedup vs baseline: 1.2017x; 1.0880x over previous
#include <cuda_runtime.h>
#include <cuda_bf16.h>
#include <cstdint>

// Problem constants (fixed by setup_inputs)
#define MAXN 100000
#define MAXE 3200000
#define FIN  512
#define H1DIM 64   // 8 heads x 8 ch
#define HEADS 8
#define C1 8
#define NCLS 16
#define MAXT (MAXE + MAXN)

// ---------------- scratch (device globals; no allocations allowed) --------
__device__ __align__(16) float g_h1[MAXN * H1DIM];     // x @ W1
__device__ __align__(16) float g_as1[MAXN * HEADS];
__device__ __align__(16) float g_ad1[MAXN * HEADS];
__device__ __align__(16) float g_denom1[MAXN * HEADS];
__device__ __align__(16) float g_out1[MAXN * H1DIM];   // layer1 unnormalized acc
__device__ __align__(16) float g_h2[MAXN * NCLS];      // elu(norm(out1)) @ W2
__device__ __align__(16) float g_as2[MAXN];
__device__ __align__(16) float g_ad2[MAXN];
__device__ __align__(16) float g_denom2[MAXN];
__device__ __align__(16) int   g_src[MAXT];
__device__ __align__(16) int   g_dst[MAXT];
__device__ int g_is64;

// vectorized L2 reduction (sm_90+)
__device__ __forceinline__ void red_add_v4(float* addr, float a, float b, float c, float d) {
    asm volatile("red.global.add.v4.f32 [%0], {%1, %2, %3, %4};"
                 :: "l"(addr), "f"(a), "f"(b), "f"(c), "f"(d) : "memory");
}
__device__ __forceinline__ void red_add_f32(float* addr, float a) {
    asm volatile("red.global.add.f32 [%0], %1;" :: "l"(addr), "f"(a) : "memory");
}

__device__ __forceinline__ float lrelu(float v) { return v > 0.f ? v : 0.2f * v; }

// bf16 mma m16n8k16, fp32 accumulate (in place)
__device__ __forceinline__ void mma_bf16(float* c, const uint32_t* a, const uint32_t* b) {
    asm volatile(
        "mma.sync.aligned.m16n8k16.row.col.f32.bf16.bf16.f32 "
        "{%0,%1,%2,%3}, {%4,%5,%6,%7}, {%8,%9}, {%0,%1,%2,%3};"
        : "+f"(c[0]), "+f"(c[1]), "+f"(c[2]), "+f"(c[3])
        : "r"(a[0]), "r"(a[1]), "r"(a[2]), "r"(a[3]), "r"(b[0]), "r"(b[1]));
}

// ---------------- dtype detect: int64 edge_index has zero high words -------
__global__ void detect_kernel(const int* __restrict__ ei32) {
    unsigned ballot = __ballot_sync(0xFFFFFFFF, ei32[2 * threadIdx.x + 1] != 0);
    if (threadIdx.x == 0) g_is64 = (ballot == 0u) ? 1 : 0;
}

// ---------------- convert edges to int32 src/dst, append self-loops --------
__global__ void convert_kernel(const void* __restrict__ ei, int E, int N) {
    int e = blockIdx.x * blockDim.x + threadIdx.x;
    int T = E + N;
    if (e >= T) return;
    if (e >= E) {
        g_src[e] = e - E;
        g_dst[e] = e - E;
        return;
    }
    if (g_is64) {
        const long long* p = (const long long*)ei;
        g_src[e] = (int)p[e];
        g_dst[e] = (int)p[(size_t)E + e];
    } else {
        const int* p = (const int*)ei;
        g_src[e] = p[e];
        g_dst[e] = p[E + e];
    }
}

// ---------------- init: zero all accumulators ------------------------------
__global__ void init_kernel(float* __restrict__ out, int N) {
    int gid = blockIdx.x * blockDim.x + threadIdx.x;
    if (gid < N * H1DIM) g_out1[gid] = 0.f;
    if (gid < N * NCLS)  out[gid]    = 0.f;
    if (gid < N * HEADS) g_denom1[gid] = 0.f;
    if (gid < N)         g_denom2[gid] = 0.f;
}

// ---------------- GEMM1 (tensor core, split-bf16): h1 = x @ W1 -------------
// 128 threads = 4 warps; warp w computes rows [w*32, w*32+32) x 64 cols.
// Split: x = xh + xl (bf16); acc += xh*Wh + xl*Wh + xh*Wl (xl*Wl ~ 2^-18, dropped)
#define GBM 128
#define SSTR 40   // smem k-stride in bf16 (20 words): conflict-free fragment LDS
__global__ __launch_bounds__(128) void gemm1_kernel(const float* __restrict__ x,
                                                    const float* __restrict__ W1, int M) {
    __shared__ __nv_bfloat16 Ah[GBM][SSTR];
    __shared__ __nv_bfloat16 Al[GBM][SSTR];
    __shared__ __nv_bfloat16 Bh[64][SSTR];
    __shared__ __nv_bfloat16 Bl[64][SSTR];
    int tid  = threadIdx.x;
    int lane = tid & 31;
    int w    = tid >> 5;
    int m0   = blockIdx.x * GBM;
    int q    = lane & 3;          // quad index
    int g    = lane >> 2;         // group (row within 8)

    float acc[2][8][4];
#pragma unroll
    for (int mt = 0; mt < 2; mt++)
#pragma unroll
        for (int nt = 0; nt < 8; nt++)
#pragma unroll
            for (int j = 0; j < 4; j++) acc[mt][nt][j] = 0.f;

    for (int k0 = 0; k0 < FIN; k0 += 32) {
        // --- A tile: 128 rows x 32 k (fp32 -> bf16 hi/lo), coalesced 64B groups
#pragma unroll
        for (int it = 0; it < 2; it++) {
#pragma unroll
            for (int pass = 0; pass < 4; pass++) {
                int row = pass * 32 + (tid >> 2);
                int c4  = (tid & 3) + it * 4;
                int gr  = m0 + row;
                float4 v = make_float4(0.f, 0.f, 0.f, 0.f);
                if (gr < M) v = *(const float4*)(x + (size_t)gr * FIN + k0 + c4 * 4);
                float vv[4] = {v.x, v.y, v.z, v.w};
#pragma unroll
                for (int j = 0; j < 4; j++) {
                    __nv_bfloat16 h = __float2bfloat16(vv[j]);
                    Ah[row][c4 * 4 + j] = h;
                    Al[row][c4 * 4 + j] = __float2bfloat16(vv[j] - __bfloat162float(h));
                }
            }
        }
        // --- B tile: 32 k-rows x 64 n, store transposed Bs[n][k]
#pragma unroll
        for (int p = 0; p < 4; p++) {
            int idx  = tid + p * 128;   // 0..511 float4 slots
            int krow = idx >> 4;        // 0..31
            int c4   = idx & 15;        // 0..15
            float4 v = *(const float4*)(W1 + (size_t)(k0 + krow) * 64 + c4 * 4);
            float vv[4] = {v.x, v.y, v.z, v.w};
#pragma unroll
            for (int j = 0; j < 4; j++) {
                __nv_bfloat16 h = __float2bfloat16(vv[j]);
                Bh[c4 * 4 + j][krow] = h;
                Bl[c4 * 4 + j][krow] = __float2bfloat16(vv[j] - __bfloat162float(h));
            }
        }
        __syncthreads();

#pragma unroll
        for (int k16 = 0; k16 < 2; k16++) {
            int kk = k16 * 16 + q * 2;
            uint32_t ah[2][4], al[2][4];
#pragma unroll
            for (int mt = 0; mt < 2; mt++) {
                int r0 = w * 32 + mt * 16 + g;
                ah[mt][0] = *(const uint32_t*)&Ah[r0][kk];
                ah[mt][1] = *(const uint32_t*)&Ah[r0 + 8][kk];
                ah[mt][2] = *(const uint32_t*)&Ah[r0][kk + 8];
                ah[mt][3] = *(const uint32_t*)&Ah[r0 + 8][kk + 8];
                al[mt][0] = *(const uint32_t*)&Al[r0][kk];
                al[mt][1] = *(const uint32_t*)&Al[r0 + 8][kk];
                al[mt][2] = *(const uint32_t*)&Al[r0][kk + 8];
                al[mt][3] = *(const uint32_t*)&Al[r0 + 8][kk + 8];
            }
#pragma unroll
            for (int nt = 0; nt < 8; nt++) {
                int nr = nt * 8 + g;
                uint32_t bh[2], bl[2];
                bh[0] = *(const uint32_t*)&Bh[nr][kk];
                bh[1] = *(const uint32_t*)&Bh[nr][kk + 8];
                bl[0] = *(const uint32_t*)&Bl[nr][kk];
                bl[1] = *(const uint32_t*)&Bl[nr][kk + 8];
#pragma unroll
                for (int mt = 0; mt < 2; mt++) {
                    mma_bf16(acc[mt][nt], ah[mt], bh);
                    mma_bf16(acc[mt][nt], al[mt], bh);
                    mma_bf16(acc[mt][nt], ah[mt], bl);
                }
            }
        }
        __syncthreads();
    }

    // --- epilogue: C fragment rows g, g+8; cols q*2, q*2+1 within each n8 tile
#pragma unroll
    for (int mt = 0; mt < 2; mt++) {
        int row0 = m0 + w * 32 + mt * 16 + g;
        int row1 = row0 + 8;
#pragma unroll
        for (int nt = 0; nt < 8; nt++) {
            int col = nt * 8 + q * 2;
            if (row0 < M)
                *(float2*)(g_h1 + (size_t)row0 * H1DIM + col) =
                    make_float2(acc[mt][nt][0], acc[mt][nt][1]);
            if (row1 < M)
                *(float2*)(g_h1 + (size_t)row1 * H1DIM + col) =
                    make_float2(acc[mt][nt][2], acc[mt][nt][3]);
        }
    }
}

// ---------------- per-node attention coefficients (layer 1) ---------------
__global__ void attn1_kernel(const float* __restrict__ att_src,
                             const float* __restrict__ att_dst, int N) {
    int idx = blockIdx.x * blockDim.x + threadIdx.x;  // n*8 + head
    if (idx >= N * HEADS) return;
    int n = idx >> 3, hh = idx & 7;
    const float* hp = g_h1 + (size_t)n * H1DIM + hh * C1;
    float4 h0 = *(const float4*)hp;
    float4 h1v = *(const float4*)(hp + 4);
    float4 s0 = *(const float4*)(att_src + hh * C1);
    float4 s1 = *(const float4*)(att_src + hh * C1 + 4);
    float4 d0 = *(const float4*)(att_dst + hh * C1);
    float4 d1 = *(const float4*)(att_dst + hh * C1 + 4);
    float as = h0.x * s0.x + h0.y * s0.y + h0.z * s0.z + h0.w * s0.w +
               h1v.x * s1.x + h1v.y * s1.y + h1v.z * s1.z + h1v.w * s1.w;
    float ad = h0.x * d0.x + h0.y * d0.y + h0.z * d0.z + h0.w * d0.w +
               h1v.x * d1.x + h1v.y * d1.y + h1v.z * d1.z + h1v.w * d1.w;
    g_as1[idx] = as;
    g_ad1[idx] = ad;
}

// ---------------- layer 1 fused: unnormalized agg + denom (8 thr/edge) ----
__global__ void edge_agg1(int T) {
    int gid = blockIdx.x * blockDim.x + threadIdx.x;
    int e = gid >> 3;
    int h = gid & 7;            // head; 8 channels each
    if (e >= T) return;
    int src = g_src[e], dst = g_dst[e];
    float w = __expf(lrelu(g_as1[(size_t)src * HEADS + h] + g_ad1[(size_t)dst * HEADS + h]));
    const float* hp = g_h1 + (size_t)src * H1DIM + h * 8;
    float4 v0 = *(const float4*)hp;
    float4 v1 = *(const float4*)(hp + 4);
    float* op = g_out1 + (size_t)dst * H1DIM + h * 8;
    red_add_v4(op, v0.x * w, v0.y * w, v0.z * w, v0.w * w);
    red_add_v4(op + 4, v1.x * w, v1.y * w, v1.z * w, v1.w * w);
    red_add_f32(g_denom1 + (size_t)dst * HEADS + h, w);
}

// ---------------- GEMM2: normalize1 + bias + elu fused on input -----------
__global__ __launch_bounds__(256) void gemm2_kernel(const float* __restrict__ W2,
                                                    const float* __restrict__ att_src2,
                                                    const float* __restrict__ att_dst2,
                                                    const float* __restrict__ b1, int N) {
    __shared__ float W2s[H1DIM * NCLS];
    __shared__ float s2[NCLS], d2[NCLS], b1s[H1DIM];
    int tid = threadIdx.x;
    for (int i = tid; i < H1DIM * NCLS; i += 256) W2s[i] = W2[i];
    if (tid < NCLS) { s2[tid] = att_src2[tid]; d2[tid] = att_dst2[tid]; }
    if (tid < H1DIM) b1s[tid] = b1[tid];
    __syncthreads();
    int n = blockIdx.x * blockDim.x + tid;
    if (n >= N) return;
    float4 dn0 = *(const float4*)(g_denom1 + (size_t)n * HEADS);
    float4 dn1 = *(const float4*)(g_denom1 + (size_t)n * HEADS + 4);
    float inv[8] = {1.f / dn0.x, 1.f / dn0.y, 1.f / dn0.z, 1.f / dn0.w,
                    1.f / dn1.x, 1.f / dn1.y, 1.f / dn1.z, 1.f / dn1.w};
    float acc[NCLS];
#pragma unroll
    for (int j = 0; j < NCLS; j++) acc[j] = 0.f;
    const float* row = g_out1 + (size_t)n * H1DIM;
#pragma unroll
    for (int c4 = 0; c4 < H1DIM / 4; c4++) {
        float4 v = *(const float4*)(row + c4 * 4);
        float vv[4] = {v.x, v.y, v.z, v.w};
#pragma unroll
        for (int u = 0; u < 4; u++) {
            int c = c4 * 4 + u;
            float val = vv[u] * inv[c >> 3] + b1s[c];      // normalize + bias
            val = val > 0.f ? val : (__expf(val) - 1.f);   // elu
#pragma unroll
            for (int j = 0; j < NCLS; j++) acc[j] += val * W2s[c * NCLS + j];
        }
    }
    float as = 0.f, ad = 0.f;
#pragma unroll
    for (int j = 0; j < NCLS; j++) { as += acc[j] * s2[j]; ad += acc[j] * d2[j]; }
    float* hp = g_h2 + (size_t)n * NCLS;
#pragma unroll
    for (int j4 = 0; j4 < NCLS / 4; j4++) {
        *(float4*)(hp + j4 * 4) = make_float4(acc[j4 * 4], acc[j4 * 4 + 1],
                                              acc[j4 * 4 + 2], acc[j4 * 4 + 3]);
    }
    g_as2[n] = as;
    g_ad2[n] = ad;
}

// ---------------- layer 2 fused: unnormalized agg + denom (4 thr/edge) ----
__global__ void edge_agg2(int T, float* __restrict__ out) {
    int gid = blockIdx.x * blockDim.x + threadIdx.x;
    int e = gid >> 2;
    int t = gid & 3;
    if (e >= T) return;
    int src = g_src[e], dst = g_dst[e];
    float w = __expf(lrelu(g_as2[src] + g_ad2[dst]));
    float4 hv = *(const float4*)(g_h2 + (size_t)src * NCLS + t * 4);
    red_add_v4(out + (size_t)dst * NCLS + t * 4,
               hv.x * w, hv.y * w, hv.z * w, hv.w * w);
    if (t == 0) red_add_f32(g_denom2 + dst, w);
}

// ---------------- layer 2: normalize + bias (in-place on out) -------------
__global__ void norm2_kernel(float* __restrict__ out, const float* __restrict__ b2, int N) {
    int gid = blockIdx.x * blockDim.x + threadIdx.x;
    if (gid >= N * NCLS) return;
    int n = gid >> 4, j = gid & 15;
    out[gid] = out[gid] / g_denom2[n] + b2[j];
}

// ---------------------------------------------------------------------------
extern "C" void kernel_launch(void* const* d_in, const int* in_sizes, int n_in,
                              void* d_out, int out_size) {
    const float* x        = (const float*)d_in[0];
    const void*  ei       = d_in[1];
    const float* W1       = (const float*)d_in[2];
    const float* att_src1 = (const float*)d_in[3];
    const float* att_dst1 = (const float*)d_in[4];
    const float* b1       = (const float*)d_in[5];
    const float* W2       = (const float*)d_in[6];
    const float* att_src2 = (const float*)d_in[7];
    const float* att_dst2 = (const float*)d_in[8];
    const float* b2       = (const float*)d_in[9];
    float* out = (float*)d_out;

    int N = in_sizes[0] / FIN;       // 100000
    int E = in_sizes[1] / 2;         // 3200000
    int T = E + N;                   // edges incl. self-loops

    detect_kernel<<<1, 32>>>((const int*)ei);
    convert_kernel<<<(T + 255) / 256, 256>>>(ei, E, N);
    init_kernel<<<(N * H1DIM + 255) / 256, 256>>>(out, N);
    gemm1_kernel<<<(N + GBM - 1) / GBM, 128>>>(x, W1, N);
    attn1_kernel<<<(N * HEADS + 255) / 256, 256>>>(att_src1, att_dst1, N);
    edge_agg1<<<((long long)T * 8 + 255) / 256, 256>>>(T);
    gemm2_kernel<<<(N + 255) / 256, 256>>>(W2, att_src2, att_dst2, b1, N);
    edge_agg2<<<((long long)T * 4 + 255) / 256, 256>>>(T, out);
    norm2_kernel<<<(N * NCLS + 255) / 256, 256>>>(out, b2, N);
}

// round 7
// speedup vs baseline: 1.8261x; 1.5197x over previous
#include <cuda_runtime.h>
#include <cuda_bf16.h>
#include <cstdint>

// Problem constants (fixed by setup_inputs)
#define MAXN 100000
#define MAXE 3200000
#define FIN  512
#define H1DIM 64   // 8 heads x 8 ch
#define HEADS 8
#define NCLS 16
#define MAXT (MAXE + MAXN)
#define SCAN_BS 1024
#define MAXB ((MAXN + SCAN_BS - 1) / SCAN_BS)

// ---------------- scratch (device globals; no allocations allowed) --------
__device__ __align__(16) float  g_h1[MAXN * H1DIM];      // x @ W1
__device__ __align__(16) float  g_out1[MAXN * H1DIM];    // layer1 NORMALIZED agg
__device__ __align__(16) float  g_h2[MAXN * NCLS];       // elu(out1+b1) @ W2
__device__ __align__(16) float4 g_atts1[MAXN * HEADS];   // {as, e^as, e^.2as, 0}
__device__ __align__(16) float4 g_attd1[MAXN * HEADS];
__device__ __align__(16) float4 g_atts2[MAXN];
__device__ __align__(16) float4 g_attd2[MAXN];
__device__ __align__(16) int g_src[MAXT];
__device__ __align__(16) int g_dst[MAXT];
__device__ __align__(16) int g_csr[MAXT];                // src sorted by dst
__device__ int g_deg[MAXN];
__device__ int g_off[MAXN];
__device__ int g_cursor[MAXN];
__device__ int g_bsum[MAXB + 1];
__device__ int g_bbase[MAXB + 1];
__device__ int g_is64;

__device__ __forceinline__ float lrelu(float v) { return v > 0.f ? v : 0.2f * v; }

__device__ __forceinline__ uint32_t sptr(const void* p) {
    return (uint32_t)__cvta_generic_to_shared(p);
}
__device__ __forceinline__ void ldsm4(uint32_t* r, uint32_t a) {
    asm volatile("ldmatrix.sync.aligned.m8n8.x4.shared.b16 {%0,%1,%2,%3}, [%4];"
        : "=r"(r[0]), "=r"(r[1]), "=r"(r[2]), "=r"(r[3]) : "r"(a));
}
__device__ __forceinline__ void ldsm4t(uint32_t* r, uint32_t a) {
    asm volatile("ldmatrix.sync.aligned.m8n8.x4.trans.shared.b16 {%0,%1,%2,%3}, [%4];"
        : "=r"(r[0]), "=r"(r[1]), "=r"(r[2]), "=r"(r[3]) : "r"(a));
}
__device__ __forceinline__ void mma_bf16(float* c, const uint32_t* a, const uint32_t* b) {
    asm volatile(
        "mma.sync.aligned.m16n8k16.row.col.f32.bf16.bf16.f32 "
        "{%0,%1,%2,%3}, {%4,%5,%6,%7}, {%8,%9}, {%0,%1,%2,%3};"
        : "+f"(c[0]), "+f"(c[1]), "+f"(c[2]), "+f"(c[3])
        : "r"(a[0]), "r"(a[1]), "r"(a[2]), "r"(a[3]), "r"(b[0]), "r"(b[1]));
}
__device__ __forceinline__ unsigned int b2u(__nv_bfloat16 a, __nv_bfloat16 b) {
    unsigned short ua = *(unsigned short*)&a, ub = *(unsigned short*)&b;
    return ((unsigned)ub << 16) | (unsigned)ua;
}

// ---------------- dtype detect: int64 edge_index has zero high words -------
__global__ void detect_kernel(const int* __restrict__ ei32) {
    unsigned ballot = __ballot_sync(0xFFFFFFFF, ei32[2 * threadIdx.x + 1] != 0);
    if (threadIdx.x == 0) g_is64 = (ballot == 0u) ? 1 : 0;
}

// ---------------- init: zero degree histogram ------------------------------
__global__ void init_kernel(int N) {
    int i = blockIdx.x * blockDim.x + threadIdx.x;
    if (i < N) g_deg[i] = 0;
}

// ---------------- convert edges + histogram over dst -----------------------
__global__ void convert_kernel(const void* __restrict__ ei, int E, int N) {
    int e = blockIdx.x * blockDim.x + threadIdx.x;
    int T = E + N;
    if (e >= T) return;
    int src, dst;
    if (e >= E) {
        src = dst = e - E;                  // self-loop
    } else if (g_is64) {
        const long long* p = (const long long*)ei;
        src = (int)p[e];
        dst = (int)p[(size_t)E + e];
    } else {
        const int* p = (const int*)ei;
        src = p[e];
        dst = p[E + e];
    }
    g_src[e] = src;
    g_dst[e] = dst;
    atomicAdd(&g_deg[dst], 1);
}

// ---------------- scan: block sums -> serial base scan -> per-block scan ---
__global__ void scanA_kernel(int N) {
    __shared__ int s[SCAN_BS];
    int i = blockIdx.x * SCAN_BS + threadIdx.x;
    s[threadIdx.x] = (i < N) ? g_deg[i] : 0;
    __syncthreads();
    for (int o = SCAN_BS / 2; o > 0; o >>= 1) {
        if (threadIdx.x < o) s[threadIdx.x] += s[threadIdx.x + o];
        __syncthreads();
    }
    if (threadIdx.x == 0) g_bsum[blockIdx.x] = s[0];
}
__global__ void scanB_kernel(int nb) {
    if (threadIdx.x == 0) {
        int run = 0;
        for (int b = 0; b < nb; b++) { g_bbase[b] = run; run += g_bsum[b]; }
    }
}
__global__ void scanC_kernel(int N) {
    __shared__ int s[SCAN_BS];
    int tid = threadIdx.x;
    int i = blockIdx.x * SCAN_BS + tid;
    int v = (i < N) ? g_deg[i] : 0;
    s[tid] = v;
    __syncthreads();
    for (int o = 1; o < SCAN_BS; o <<= 1) {
        int t = (tid >= o) ? s[tid - o] : 0;
        __syncthreads();
        s[tid] += t;
        __syncthreads();
    }
    if (i < N) {
        int off = g_bbase[blockIdx.x] + s[tid] - v;   // exclusive prefix
        g_off[i] = off;
        g_cursor[i] = off;
    }
}

// ---------------- scatter edges into CSR by dst ----------------------------
__global__ void scatter_kernel(int T) {
    int e = blockIdx.x * blockDim.x + threadIdx.x;
    if (e >= T) return;
    int dst = g_dst[e];
    int slot = atomicAdd(&g_cursor[dst], 1);
    g_csr[slot] = g_src[e];
}
// after scatter: g_cursor[d] == g_off[d] + deg[d] == row end

// ---------------- GEMM1 (tensor core, split-bf16, ldmatrix) ---------------
// 128 threads = 4 warps; warp w -> rows [w*32, w*32+32) x 64 cols.
// x = xh + xl (bf16); acc += xh*Wh + xl*Wh + xh*Wl
#define GBM 128
#define ASTR 40     // A smem row stride (bf16): 80B rows, ldmatrix conflict-free
#define BSTR 72     // B smem row stride (bf16): 144B rows, trans-ldmatrix conflict-free
__global__ __launch_bounds__(128) void gemm1_kernel(const float* __restrict__ x,
                                                    const float* __restrict__ W1, int M) {
    __shared__ __align__(16) __nv_bfloat16 Ah[GBM][ASTR];
    __shared__ __align__(16) __nv_bfloat16 Al[GBM][ASTR];
    __shared__ __align__(16) __nv_bfloat16 Bh[32][BSTR];   // [k][n]
    __shared__ __align__(16) __nv_bfloat16 Bl[32][BSTR];
    int tid  = threadIdx.x;
    int lane = tid & 31;
    int wid  = tid >> 5;
    int m0   = blockIdx.x * GBM;
    int q    = lane & 3;
    int g    = lane >> 2;

    float acc[2][8][4];
#pragma unroll
    for (int mt = 0; mt < 2; mt++)
#pragma unroll
        for (int nt = 0; nt < 8; nt++)
#pragma unroll
            for (int j = 0; j < 4; j++) acc[mt][nt][j] = 0.f;

    for (int k0 = 0; k0 < FIN; k0 += 32) {
        // --- A tile: 128 rows x 32 k; packed 8B smem stores
#pragma unroll
        for (int it = 0; it < 2; it++) {
#pragma unroll
            for (int pass = 0; pass < 4; pass++) {
                int row = pass * 32 + (tid >> 2);
                int c4  = (tid & 3) + it * 4;
                int gr  = m0 + row;
                float4 v = make_float4(0.f, 0.f, 0.f, 0.f);
                if (gr < M) v = *(const float4*)(x + (size_t)gr * FIN + k0 + c4 * 4);
                float vv[4] = {v.x, v.y, v.z, v.w};
                __nv_bfloat16 hb[4], lb[4];
#pragma unroll
                for (int j = 0; j < 4; j++) {
                    hb[j] = __float2bfloat16(vv[j]);
                    lb[j] = __float2bfloat16(vv[j] - __bfloat162float(hb[j]));
                }
                uint2 uh = make_uint2(b2u(hb[0], hb[1]), b2u(hb[2], hb[3]));
                uint2 ul = make_uint2(b2u(lb[0], lb[1]), b2u(lb[2], lb[3]));
                *(uint2*)&Ah[row][c4 * 4] = uh;
                *(uint2*)&Al[row][c4 * 4] = ul;
            }
        }
        // --- B tile: 32 k-rows x 64 n, natural [k][n]; packed 8B stores
#pragma unroll
        for (int p = 0; p < 4; p++) {
            int t  = tid + p * 128;
            int kr = t >> 4;       // 0..31
            int c4 = t & 15;
            float4 v = *(const float4*)(W1 + (size_t)(k0 + kr) * 64 + c4 * 4);
            float vv[4] = {v.x, v.y, v.z, v.w};
            __nv_bfloat16 hb[4], lb[4];
#pragma unroll
            for (int j = 0; j < 4; j++) {
                hb[j] = __float2bfloat16(vv[j]);
                lb[j] = __float2bfloat16(vv[j] - __bfloat162float(hb[j]));
            }
            *(uint2*)&Bh[kr][c4 * 4] = make_uint2(b2u(hb[0], hb[1]), b2u(hb[2], hb[3]));
            *(uint2*)&Bl[kr][c4 * 4] = make_uint2(b2u(lb[0], lb[1]), b2u(lb[2], lb[3]));
        }
        __syncthreads();

#pragma unroll
        for (int k16 = 0; k16 < 2; k16++) {
            int kkB = k16 * 16;
            // A fragments via ldmatrix.x4 (mats: m0-7/k0, m8-15/k0, m0-7/k8, m8-15/k8)
            uint32_t ah[2][4], al[2][4];
            int arow = lane & 15;
            int akk  = kkB + ((lane & 16) ? 8 : 0);
#pragma unroll
            for (int mt = 0; mt < 2; mt++) {
                ldsm4(ah[mt], sptr(&Ah[wid * 32 + mt * 16 + arow][akk]));
                ldsm4(al[mt], sptr(&Al[wid * 32 + mt * 16 + arow][akk]));
            }
            // B fragments via trans ldmatrix.x4 (2 nt tiles per load)
#pragma unroll
            for (int p = 0; p < 4; p++) {
                int bk = kkB + (lane & 7) + ((lane & 8) ? 8 : 0);
                int bn = p * 16 + ((lane & 16) ? 8 : 0);
                uint32_t bh[4], bl[4];
                ldsm4t(bh, sptr(&Bh[bk][bn]));
                ldsm4t(bl, sptr(&Bl[bk][bn]));
#pragma unroll
                for (int mt = 0; mt < 2; mt++) {
                    mma_bf16(acc[mt][2 * p],     ah[mt], bh);
                    mma_bf16(acc[mt][2 * p],     al[mt], bh);
                    mma_bf16(acc[mt][2 * p],     ah[mt], bl);
                    mma_bf16(acc[mt][2 * p + 1], ah[mt], bh + 2);
                    mma_bf16(acc[mt][2 * p + 1], al[mt], bh + 2);
                    mma_bf16(acc[mt][2 * p + 1], ah[mt], bl + 2);
                }
            }
        }
        __syncthreads();
    }

#pragma unroll
    for (int mt = 0; mt < 2; mt++) {
        int row0 = m0 + wid * 32 + mt * 16 + g;
        int row1 = row0 + 8;
#pragma unroll
        for (int nt = 0; nt < 8; nt++) {
            int col = nt * 8 + q * 2;
            if (row0 < M)
                *(float2*)(g_h1 + (size_t)row0 * H1DIM + col) =
                    make_float2(acc[mt][nt][0], acc[mt][nt][1]);
            if (row1 < M)
                *(float2*)(g_h1 + (size_t)row1 * H1DIM + col) =
                    make_float2(acc[mt][nt][2], acc[mt][nt][3]);
        }
    }
}

// ---------------- attention coefficients + exp tables (layer 1) -----------
__global__ void attn1_kernel(const float* __restrict__ att_src,
                             const float* __restrict__ att_dst, int N) {
    int idx = blockIdx.x * blockDim.x + threadIdx.x;  // n*8 + head
    if (idx >= N * HEADS) return;
    int n = idx >> 3, hh = idx & 7;
    const float* hp = g_h1 + (size_t)n * H1DIM + hh * 8;
    float4 h0 = *(const float4*)hp;
    float4 h1v = *(const float4*)(hp + 4);
    float4 s0 = *(const float4*)(att_src + hh * 8);
    float4 s1 = *(const float4*)(att_src + hh * 8 + 4);
    float4 d0 = *(const float4*)(att_dst + hh * 8);
    float4 d1 = *(const float4*)(att_dst + hh * 8 + 4);
    float as = h0.x * s0.x + h0.y * s0.y + h0.z * s0.z + h0.w * s0.w +
               h1v.x * s1.x + h1v.y * s1.y + h1v.z * s1.z + h1v.w * s1.w;
    float ad = h0.x * d0.x + h0.y * d0.y + h0.z * d0.z + h0.w * d0.w +
               h1v.x * d1.x + h1v.y * d1.y + h1v.z * d1.z + h1v.w * d1.w;
    g_atts1[idx] = make_float4(as, __expf(as), __expf(0.2f * as), 0.f);
    g_attd1[idx] = make_float4(ad, __expf(ad), __expf(0.2f * ad), 0.f);
}

// ---------------- layer 1 gather: agg + softmax (8 thr/dst, no atomics) ---
__global__ __launch_bounds__(256) void gather1_kernel(int N) {
    int gid = blockIdx.x * blockDim.x + threadIdx.x;
    int dst = gid >> 3;
    int h   = gid & 7;
    if (dst >= N) return;
    float4 da = g_attd1[(size_t)dst * HEADS + h];   // {ad, e^ad, e^.2ad}
    int beg = g_off[dst];
    int end = g_cursor[dst];
    float4 a0 = make_float4(0.f, 0.f, 0.f, 0.f);
    float4 a1 = make_float4(0.f, 0.f, 0.f, 0.f);
    float denom = 0.f;
    int src = g_csr[beg];
    for (int i = beg; i < end; i++) {
        int nsrc = (i + 1 < end) ? g_csr[i + 1] : 0;
        float4 sa = g_atts1[(size_t)src * HEADS + h];
        float w = (sa.x + da.x > 0.f) ? sa.y * da.y : sa.z * da.z;
        const float* hp = g_h1 + (size_t)src * H1DIM + h * 8;
        float4 v0 = *(const float4*)hp;
        float4 v1 = *(const float4*)(hp + 4);
        a0.x += w * v0.x; a0.y += w * v0.y; a0.z += w * v0.z; a0.w += w * v0.w;
        a1.x += w * v1.x; a1.y += w * v1.y; a1.z += w * v1.z; a1.w += w * v1.w;
        denom += w;
        src = nsrc;
    }
    float inv = 1.f / denom;
    float* op = g_out1 + (size_t)dst * H1DIM + h * 8;
    *(float4*)op       = make_float4(a0.x * inv, a0.y * inv, a0.z * inv, a0.w * inv);
    *(float4*)(op + 4) = make_float4(a1.x * inv, a1.y * inv, a1.z * inv, a1.w * inv);
}

// ---------------- GEMM2: bias + elu fused; attn2 exp tables ---------------
__global__ __launch_bounds__(256) void gemm2_kernel(const float* __restrict__ W2,
                                                    const float* __restrict__ att_src2,
                                                    const float* __restrict__ att_dst2,
                                                    const float* __restrict__ b1, int N) {
    __shared__ float W2s[H1DIM * NCLS];
    __shared__ float s2[NCLS], d2[NCLS], b1s[H1DIM];
    int tid = threadIdx.x;
    for (int i = tid; i < H1DIM * NCLS; i += 256) W2s[i] = W2[i];
    if (tid < NCLS) { s2[tid] = att_src2[tid]; d2[tid] = att_dst2[tid]; }
    if (tid < H1DIM) b1s[tid] = b1[tid];
    __syncthreads();
    int n = blockIdx.x * blockDim.x + tid;
    if (n >= N) return;
    float acc[NCLS];
#pragma unroll
    for (int j = 0; j < NCLS; j++) acc[j] = 0.f;
    const float* row = g_out1 + (size_t)n * H1DIM;   // already normalized
#pragma unroll
    for (int c4 = 0; c4 < H1DIM / 4; c4++) {
        float4 v = *(const float4*)(row + c4 * 4);
        float vv[4] = {v.x, v.y, v.z, v.w};
#pragma unroll
        for (int u = 0; u < 4; u++) {
            int c = c4 * 4 + u;
            float val = vv[u] + b1s[c];
            val = val > 0.f ? val : (__expf(val) - 1.f);   // elu
#pragma unroll
            for (int j = 0; j < NCLS; j++) acc[j] += val * W2s[c * NCLS + j];
        }
    }
    float as = 0.f, ad = 0.f;
#pragma unroll
    for (int j = 0; j < NCLS; j++) { as += acc[j] * s2[j]; ad += acc[j] * d2[j]; }
    float* hp = g_h2 + (size_t)n * NCLS;
#pragma unroll
    for (int j4 = 0; j4 < NCLS / 4; j4++)
        *(float4*)(hp + j4 * 4) = make_float4(acc[j4 * 4], acc[j4 * 4 + 1],
                                              acc[j4 * 4 + 2], acc[j4 * 4 + 3]);
    g_atts2[n] = make_float4(as, __expf(as), __expf(0.2f * as), 0.f);
    g_attd2[n] = make_float4(ad, __expf(ad), __expf(0.2f * ad), 0.f);
}

// ---------------- layer 2 gather: agg + softmax + bias (4 thr/dst) --------
__global__ __launch_bounds__(256) void gather2_kernel(int N, const float* __restrict__ b2,
                                                      float* __restrict__ out) {
    int gid = blockIdx.x * blockDim.x + threadIdx.x;
    int dst = gid >> 2;
    int t   = gid & 3;
    if (dst >= N) return;
    float4 da = g_attd2[dst];
    float4 bv = *(const float4*)(b2 + t * 4);
    int beg = g_off[dst];
    int end = g_cursor[dst];
    float4 a = make_float4(0.f, 0.f, 0.f, 0.f);
    float denom = 0.f;
    int src = g_csr[beg];
    for (int i = beg; i < end; i++) {
        int nsrc = (i + 1 < end) ? g_csr[i + 1] : 0;
        float4 sa = g_atts2[src];
        float w = (sa.x + da.x > 0.f) ? sa.y * da.y : sa.z * da.z;
        float4 v = *(const float4*)(g_h2 + (size_t)src * NCLS + t * 4);
        a.x += w * v.x; a.y += w * v.y; a.z += w * v.z; a.w += w * v.w;
        denom += w;
        src = nsrc;
    }
    float inv = 1.f / denom;
    *(float4*)(out + (size_t)dst * NCLS + t * 4) =
        make_float4(a.x * inv + bv.x, a.y * inv + bv.y,
                    a.z * inv + bv.z, a.w * inv + bv.w);
}

// ---------------------------------------------------------------------------
extern "C" void kernel_launch(void* const* d_in, const int* in_sizes, int n_in,
                              void* d_out, int out_size) {
    const float* x        = (const float*)d_in[0];
    const void*  ei       = d_in[1];
    const float* W1       = (const float*)d_in[2];
    const float* att_src1 = (const float*)d_in[3];
    const float* att_dst1 = (const float*)d_in[4];
    const float* b1       = (const float*)d_in[5];
    const float* W2       = (const float*)d_in[6];
    const float* att_src2 = (const float*)d_in[7];
    const float* att_dst2 = (const float*)d_in[8];
    const float* b2       = (const float*)d_in[9];
    float* out = (float*)d_out;

    int N = in_sizes[0] / FIN;       // 100000
    int E = in_sizes[1] / 2;         // 3200000
    int T = E + N;
    int nb = (N + SCAN_BS - 1) / SCAN_BS;

    detect_kernel<<<1, 32>>>((const int*)ei);
    init_kernel<<<(N + 255) / 256, 256>>>(N);
    convert_kernel<<<(T + 255) / 256, 256>>>(ei, E, N);
    scanA_kernel<<<nb, SCAN_BS>>>(N);
    scanB_kernel<<<1, 32>>>(nb);
    scanC_kernel<<<nb, SCAN_BS>>>(N);
    scatter_kernel<<<(T + 255) / 256, 256>>>(T);
    gemm1_kernel<<<(N + GBM - 1) / GBM, 128>>>(x, W1, N);
    attn1_kernel<<<(N * HEADS + 255) / 256, 256>>>(att_src1, att_dst1, N);
    gather1_kernel<<<((long long)N * 8 + 255) / 256, 256>>>(N);
    gemm2_kernel<<<(N + 255) / 256, 256>>>(W2, att_src2, att_dst2, b1, N);
    gather2_kernel<<<((long long)N * 4 + 255) / 256, 256>>>(N, b2, out);
}

// round 9
// speedup vs baseline: 2.0696x; 1.1333x over previous
#include <cuda_runtime.h>
#include <cuda_bf16.h>
#include <cstdint>

// Problem constants (fixed by setup_inputs)
#define MAXN 100000
#define MAXE 3200000
#define FIN  512
#define H1DIM 64   // 8 heads x 8 ch
#define HEADS 8
#define NCLS 16
#define MAXT (MAXE + MAXN)
#define SCAN_BS 1024
#define MAXB ((MAXN + SCAN_BS - 1) / SCAN_BS)

// ---------------- scratch (device globals; no allocations allowed) --------
__device__ __align__(16) float  g_h1[MAXN * H1DIM];      // x @ W1
__device__ __align__(16) float  g_out1[MAXN * H1DIM];    // layer1 NORMALIZED agg
__device__ __align__(16) float  g_h2[MAXN * NCLS];       // elu(out1+b1) @ W2
__device__ __align__(16) float2 g_as1e[MAXN * HEADS];    // {e^as, e^0.2as}
__device__ __align__(16) float2 g_ad1e[MAXN * HEADS];
__device__ __align__(16) float2 g_as2e[MAXN];
__device__ __align__(16) float2 g_ad2e[MAXN];
__device__ __align__(16) int g_src[MAXT];
__device__ __align__(16) int g_dst[MAXT];
__device__ __align__(16) int g_csr[MAXT];                // src sorted by dst
__device__ int g_deg[MAXN];
__device__ int g_off[MAXN];
__device__ int g_cursor[MAXN];
__device__ int g_bsum[MAXB + 1];
__device__ int g_bbase[MAXB + 1];
__device__ int g_is64;

__device__ __forceinline__ uint32_t sptr(const void* p) {
    return (uint32_t)__cvta_generic_to_shared(p);
}
__device__ __forceinline__ void ldsm4(uint32_t* r, uint32_t a) {
    asm volatile("ldmatrix.sync.aligned.m8n8.x4.shared.b16 {%0,%1,%2,%3}, [%4];"
        : "=r"(r[0]), "=r"(r[1]), "=r"(r[2]), "=r"(r[3]) : "r"(a));
}
__device__ __forceinline__ void ldsm4t(uint32_t* r, uint32_t a) {
    asm volatile("ldmatrix.sync.aligned.m8n8.x4.trans.shared.b16 {%0,%1,%2,%3}, [%4];"
        : "=r"(r[0]), "=r"(r[1]), "=r"(r[2]), "=r"(r[3]) : "r"(a));
}
__device__ __forceinline__ void mma_bf16(float* c, const uint32_t* a, const uint32_t* b) {
    asm volatile(
        "mma.sync.aligned.m16n8k16.row.col.f32.bf16.bf16.f32 "
        "{%0,%1,%2,%3}, {%4,%5,%6,%7}, {%8,%9}, {%0,%1,%2,%3};"
        : "+f"(c[0]), "+f"(c[1]), "+f"(c[2]), "+f"(c[3])
        : "r"(a[0]), "r"(a[1]), "r"(a[2]), "r"(a[3]), "r"(b[0]), "r"(b[1]));
}
__device__ __forceinline__ unsigned int b2u(__nv_bfloat16 a, __nv_bfloat16 b) {
    unsigned short ua = *(unsigned short*)&a, ub = *(unsigned short*)&b;
    return ((unsigned)ub << 16) | (unsigned)ua;
}
__device__ __forceinline__ float qreduce(float v) {   // sum over quad (lanes ^1, ^2)
    v += __shfl_xor_sync(0xFFFFFFFF, v, 1);
    v += __shfl_xor_sync(0xFFFFFFFF, v, 2);
    return v;
}

// ---------------- dtype detect: int64 edge_index has zero high words -------
__global__ void detect_kernel(const int* __restrict__ ei32) {
    unsigned ballot = __ballot_sync(0xFFFFFFFF, ei32[2 * threadIdx.x + 1] != 0);
    if (threadIdx.x == 0) g_is64 = (ballot == 0u) ? 1 : 0;
}

// ---------------- init: zero degree histogram ------------------------------
__global__ void init_kernel(int N) {
    int i = blockIdx.x * blockDim.x + threadIdx.x;
    if (i < N) g_deg[i] = 0;
}

// ---------------- convert edges + histogram over dst -----------------------
__global__ void convert_kernel(const void* __restrict__ ei, int E, int N) {
    int e = blockIdx.x * blockDim.x + threadIdx.x;
    int T = E + N;
    if (e >= T) return;
    int src, dst;
    if (e >= E) {
        src = dst = e - E;                  // self-loop
    } else if (g_is64) {
        const long long* p = (const long long*)ei;
        src = (int)p[e];
        dst = (int)p[(size_t)E + e];
    } else {
        const int* p = (const int*)ei;
        src = p[e];
        dst = p[E + e];
    }
    g_src[e] = src;
    g_dst[e] = dst;
    atomicAdd(&g_deg[dst], 1);
}

// ---------------- scan: block sums -> base scan -> per-block scan ----------
__global__ void scanA_kernel(int N) {
    __shared__ int s[SCAN_BS];
    int i = blockIdx.x * SCAN_BS + threadIdx.x;
    s[threadIdx.x] = (i < N) ? g_deg[i] : 0;
    __syncthreads();
    for (int o = SCAN_BS / 2; o > 0; o >>= 1) {
        if (threadIdx.x < o) s[threadIdx.x] += s[threadIdx.x + o];
        __syncthreads();
    }
    if (threadIdx.x == 0) g_bsum[blockIdx.x] = s[0];
}
__global__ void scanB_kernel(int nb) {   // nb <= 128
    __shared__ int s[128];
    int t = threadIdx.x;
    int v = (t < nb) ? g_bsum[t] : 0;
    s[t] = v;
    __syncthreads();
    for (int o = 1; o < 128; o <<= 1) {
        int u = (t >= o) ? s[t - o] : 0;
        __syncthreads();
        s[t] += u;
        __syncthreads();
    }
    if (t < nb) g_bbase[t] = s[t] - v;   // exclusive
}
__global__ void scanC_kernel(int N) {
    __shared__ int s[SCAN_BS];
    int tid = threadIdx.x;
    int i = blockIdx.x * SCAN_BS + tid;
    int v = (i < N) ? g_deg[i] : 0;
    s[tid] = v;
    __syncthreads();
    for (int o = 1; o < SCAN_BS; o <<= 1) {
        int t = (tid >= o) ? s[tid - o] : 0;
        __syncthreads();
        s[tid] += t;
        __syncthreads();
    }
    if (i < N) {
        int off = g_bbase[blockIdx.x] + s[tid] - v;   // exclusive prefix
        g_off[i] = off;
        g_cursor[i] = off;
    }
}

// ---------------- scatter edges into CSR by dst ----------------------------
__global__ void scatter_kernel(int T) {
    int e = blockIdx.x * blockDim.x + threadIdx.x;
    if (e >= T) return;
    int dst = g_dst[e];
    int slot = atomicAdd(&g_cursor[dst], 1);
    g_csr[slot] = g_src[e];
}
// after scatter: g_cursor[d] == g_off[d] + deg[d] == row end

// ---------------- GEMM1 (tensor core, split-bf16) + fused attn1 -----------
// 128 threads = 4 warps; warp w -> rows [w*32, w*32+32) x 64 cols.
// x = xh + xl (bf16); acc += xh*Wh + xl*Wh + xh*Wl
// Epilogue also computes as/ad per (row, head) and writes exp tables.
#define GBM 128
#define ASTR 40     // A smem row stride (bf16)
#define BSTR 72     // B smem row stride (bf16)
__global__ __launch_bounds__(128) void gemm1_kernel(const float* __restrict__ x,
                                                    const float* __restrict__ W1,
                                                    const float* __restrict__ att_src,
                                                    const float* __restrict__ att_dst,
                                                    int M) {
    __shared__ __align__(16) __nv_bfloat16 Ah[GBM][ASTR];
    __shared__ __align__(16) __nv_bfloat16 Al[GBM][ASTR];
    __shared__ __align__(16) __nv_bfloat16 Bh[32][BSTR];   // [k][n]
    __shared__ __align__(16) __nv_bfloat16 Bl[32][BSTR];
    __shared__ float s_as[H1DIM], s_ad[H1DIM];
    int tid  = threadIdx.x;
    int lane = tid & 31;
    int wid  = tid >> 5;
    int m0   = blockIdx.x * GBM;
    int q    = lane & 3;
    int g    = lane >> 2;

    if (tid < H1DIM) { s_as[tid] = att_src[tid]; s_ad[tid] = att_dst[tid]; }

    float acc[2][8][4];
#pragma unroll
    for (int mt = 0; mt < 2; mt++)
#pragma unroll
        for (int nt = 0; nt < 8; nt++)
#pragma unroll
            for (int j = 0; j < 4; j++) acc[mt][nt][j] = 0.f;

    for (int k0 = 0; k0 < FIN; k0 += 32) {
        // --- A tile: 128 rows x 32 k; packed 8B smem stores
#pragma unroll
        for (int it = 0; it < 2; it++) {
#pragma unroll
            for (int pass = 0; pass < 4; pass++) {
                int row = pass * 32 + (tid >> 2);
                int c4  = (tid & 3) + it * 4;
                int gr  = m0 + row;
                float4 v = make_float4(0.f, 0.f, 0.f, 0.f);
                if (gr < M) v = *(const float4*)(x + (size_t)gr * FIN + k0 + c4 * 4);
                float vv[4] = {v.x, v.y, v.z, v.w};
                __nv_bfloat16 hb[4], lb[4];
#pragma unroll
                for (int j = 0; j < 4; j++) {
                    hb[j] = __float2bfloat16(vv[j]);
                    lb[j] = __float2bfloat16(vv[j] - __bfloat162float(hb[j]));
                }
                *(uint2*)&Ah[row][c4 * 4] = make_uint2(b2u(hb[0], hb[1]), b2u(hb[2], hb[3]));
                *(uint2*)&Al[row][c4 * 4] = make_uint2(b2u(lb[0], lb[1]), b2u(lb[2], lb[3]));
            }
        }
        // --- B tile: 32 k-rows x 64 n, natural [k][n]; packed 8B stores
#pragma unroll
        for (int p = 0; p < 4; p++) {
            int t  = tid + p * 128;
            int kr = t >> 4;       // 0..31
            int c4 = t & 15;
            float4 v = *(const float4*)(W1 + (size_t)(k0 + kr) * 64 + c4 * 4);
            float vv[4] = {v.x, v.y, v.z, v.w};
            __nv_bfloat16 hb[4], lb[4];
#pragma unroll
            for (int j = 0; j < 4; j++) {
                hb[j] = __float2bfloat16(vv[j]);
                lb[j] = __float2bfloat16(vv[j] - __bfloat162float(hb[j]));
            }
            *(uint2*)&Bh[kr][c4 * 4] = make_uint2(b2u(hb[0], hb[1]), b2u(hb[2], hb[3]));
            *(uint2*)&Bl[kr][c4 * 4] = make_uint2(b2u(lb[0], lb[1]), b2u(lb[2], lb[3]));
        }
        __syncthreads();

#pragma unroll
        for (int k16 = 0; k16 < 2; k16++) {
            int kkB = k16 * 16;
            uint32_t ah[2][4], al[2][4];
            int arow = lane & 15;
            int akk  = kkB + ((lane & 16) ? 8 : 0);
#pragma unroll
            for (int mt = 0; mt < 2; mt++) {
                ldsm4(ah[mt], sptr(&Ah[wid * 32 + mt * 16 + arow][akk]));
                ldsm4(al[mt], sptr(&Al[wid * 32 + mt * 16 + arow][akk]));
            }
#pragma unroll
            for (int p = 0; p < 4; p++) {
                int bk = kkB + (lane & 7) + ((lane & 8) ? 8 : 0);
                int bn = p * 16 + ((lane & 16) ? 8 : 0);
                uint32_t bh[4], bl[4];
                ldsm4t(bh, sptr(&Bh[bk][bn]));
                ldsm4t(bl, sptr(&Bl[bk][bn]));
#pragma unroll
                for (int mt = 0; mt < 2; mt++) {
                    mma_bf16(acc[mt][2 * p],     ah[mt], bh);
                    mma_bf16(acc[mt][2 * p],     al[mt], bh);
                    mma_bf16(acc[mt][2 * p],     ah[mt], bl);
                    mma_bf16(acc[mt][2 * p + 1], ah[mt], bh + 2);
                    mma_bf16(acc[mt][2 * p + 1], al[mt], bh + 2);
                    mma_bf16(acc[mt][2 * p + 1], ah[mt], bl + 2);
                }
            }
        }
        __syncthreads();
    }

    // --- epilogue: write h1 + fused per-head attention exp tables
#pragma unroll
    for (int mt = 0; mt < 2; mt++) {
        int row0 = m0 + wid * 32 + mt * 16 + g;
        int row1 = row0 + 8;
#pragma unroll
        for (int nt = 0; nt < 8; nt++) {
            int col = nt * 8 + q * 2;
            if (row0 < M)
                *(float2*)(g_h1 + (size_t)row0 * H1DIM + col) =
                    make_float2(acc[mt][nt][0], acc[mt][nt][1]);
            if (row1 < M)
                *(float2*)(g_h1 + (size_t)row1 * H1DIM + col) =
                    make_float2(acc[mt][nt][2], acc[mt][nt][3]);
            // attention dots for head nt (cols nt*8..nt*8+7)
            float sa0 = s_as[col], sa1 = s_as[col + 1];
            float sd0 = s_ad[col], sd1 = s_ad[col + 1];
            float pas0 = qreduce(acc[mt][nt][0] * sa0 + acc[mt][nt][1] * sa1);
            float pad0 = qreduce(acc[mt][nt][0] * sd0 + acc[mt][nt][1] * sd1);
            float pas1 = qreduce(acc[mt][nt][2] * sa0 + acc[mt][nt][3] * sa1);
            float pad1 = qreduce(acc[mt][nt][2] * sd0 + acc[mt][nt][3] * sd1);
            float v   = (q == 0) ? pas0 : (q == 1) ? pad0 : (q == 2) ? pas1 : pad1;
            int   row = (q < 2) ? row0 : row1;
            float2* tab = (q & 1) ? g_ad1e : g_as1e;
            if (row < M)
                tab[(size_t)row * HEADS + nt] = make_float2(__expf(v), __expf(0.2f * v));
        }
    }
}

// ---------------- layer 1 gather: agg + softmax (8 thr/dst, no atomics) ---
__global__ __launch_bounds__(256) void gather1_kernel(int N) {
    int gid = blockIdx.x * blockDim.x + threadIdx.x;
    int dst = gid >> 3;
    int h   = gid & 7;
    if (dst >= N) return;
    float2 da = g_ad1e[(size_t)dst * HEADS + h];
    int beg = g_off[dst];
    int end = g_cursor[dst];
    float4 a0 = make_float4(0.f, 0.f, 0.f, 0.f);
    float4 a1 = make_float4(0.f, 0.f, 0.f, 0.f);
    float denom = 0.f;
    for (int i = beg; i < end; i++) {
        int src = g_csr[i];
        float2 sa = g_as1e[(size_t)src * HEADS + h];
        float w = fmaxf(sa.x * da.x, sa.y * da.y);   // e^lrelu(as+ad)
        const float* hp = g_h1 + (size_t)src * H1DIM + h * 8;
        float4 v0 = *(const float4*)hp;
        float4 v1 = *(const float4*)(hp + 4);
        a0.x += w * v0.x; a0.y += w * v0.y; a0.z += w * v0.z; a0.w += w * v0.w;
        a1.x += w * v1.x; a1.y += w * v1.y; a1.z += w * v1.z; a1.w += w * v1.w;
        denom += w;
    }
    float inv = 1.f / denom;
    float* op = g_out1 + (size_t)dst * H1DIM + h * 8;
    *(float4*)op       = make_float4(a0.x * inv, a0.y * inv, a0.z * inv, a0.w * inv);
    *(float4*)(op + 4) = make_float4(a1.x * inv, a1.y * inv, a1.z * inv, a1.w * inv);
}

// ---------------- GEMM2: bias + elu fused; attn2 exp tables ---------------
__global__ __launch_bounds__(256) void gemm2_kernel(const float* __restrict__ W2,
                                                    const float* __restrict__ att_src2,
                                                    const float* __restrict__ att_dst2,
                                                    const float* __restrict__ b1, int N) {
    __shared__ float W2s[H1DIM * NCLS];
    __shared__ float s2[NCLS], d2[NCLS], b1s[H1DIM];
    int tid = threadIdx.x;
    for (int i = tid; i < H1DIM * NCLS; i += 256) W2s[i] = W2[i];
    if (tid < NCLS) { s2[tid] = att_src2[tid]; d2[tid] = att_dst2[tid]; }
    if (tid < H1DIM) b1s[tid] = b1[tid];
    __syncthreads();
    int n = blockIdx.x * blockDim.x + tid;
    if (n >= N) return;
    float acc[NCLS];
#pragma unroll
    for (int j = 0; j < NCLS; j++) acc[j] = 0.f;
    const float* row = g_out1 + (size_t)n * H1DIM;   // already normalized
#pragma unroll
    for (int c4 = 0; c4 < H1DIM / 4; c4++) {
        float4 v = *(const float4*)(row + c4 * 4);
        float vv[4] = {v.x, v.y, v.z, v.w};
#pragma unroll
        for (int u = 0; u < 4; u++) {
            int c = c4 * 4 + u;
            float val = vv[u] + b1s[c];
            val = val > 0.f ? val : (__expf(val) - 1.f);   // elu
#pragma unroll
            for (int j = 0; j < NCLS; j++) acc[j] += val * W2s[c * NCLS + j];
        }
    }
    float as = 0.f, ad = 0.f;
#pragma unroll
    for (int j = 0; j < NCLS; j++) { as += acc[j] * s2[j]; ad += acc[j] * d2[j]; }
    float* hp = g_h2 + (size_t)n * NCLS;
#pragma unroll
    for (int j4 = 0; j4 < NCLS / 4; j4++)
        *(float4*)(hp + j4 * 4) = make_float4(acc[j4 * 4], acc[j4 * 4 + 1],
                                              acc[j4 * 4 + 2], acc[j4 * 4 + 3]);
    g_as2e[n] = make_float2(__expf(as), __expf(0.2f * as));
    g_ad2e[n] = make_float2(__expf(ad), __expf(0.2f * ad));
}

// ---------------- layer 2 gather: agg + softmax + bias (4 thr/dst) --------
__global__ __launch_bounds__(256) void gather2_kernel(int N, const float* __restrict__ b2,
                                                      float* __restrict__ out) {
    int gid = blockIdx.x * blockDim.x + threadIdx.x;
    int dst = gid >> 2;
    int t   = gid & 3;
    if (dst >= N) return;
    float2 da = g_ad2e[dst];
    float4 bv = *(const float4*)(b2 + t * 4);
    int beg = g_off[dst];
    int end = g_cursor[dst];
    float4 a = make_float4(0.f, 0.f, 0.f, 0.f);
    float denom = 0.f;
    for (int i = beg; i < end; i++) {
        int src = g_csr[i];
        float2 sa = g_as2e[src];
        float w = fmaxf(sa.x * da.x, sa.y * da.y);
        float4 v = *(const float4*)(g_h2 + (size_t)src * NCLS + t * 4);
        a.x += w * v.x; a.y += w * v.y; a.z += w * v.z; a.w += w * v.w;
        denom += w;
    }
    float inv = 1.f / denom;
    *(float4*)(out + (size_t)dst * NCLS + t * 4) =
        make_float4(a.x * inv + bv.x, a.y * inv + bv.y,
                    a.z * inv + bv.z, a.w * inv + bv.w);
}

// ---------------------------------------------------------------------------
extern "C" void kernel_launch(void* const* d_in, const int* in_sizes, int n_in,
                              void* d_out, int out_size) {
    const float* x        = (const float*)d_in[0];
    const void*  ei       = d_in[1];
    const float* W1       = (const float*)d_in[2];
    const float* att_src1 = (const float*)d_in[3];
    const float* att_dst1 = (const float*)d_in[4];
    const float* b1       = (const float*)d_in[5];
    const float* W2       = (const float*)d_in[6];
    const float* att_src2 = (const float*)d_in[7];
    const float* att_dst2 = (const float*)d_in[8];
    const float* b2       = (const float*)d_in[9];
    float* out = (float*)d_out;

    int N = in_sizes[0] / FIN;       // 100000
    int E = in_sizes[1] / 2;         // 3200000
    int T = E + N;
    int nb = (N + SCAN_BS - 1) / SCAN_BS;

    detect_kernel<<<1, 32>>>((const int*)ei);
    init_kernel<<<(N + 255) / 256, 256>>>(N);
    convert_kernel<<<(T + 255) / 256, 256>>>(ei, E, N);
    scanA_kernel<<<nb, SCAN_BS>>>(N);
    scanB_kernel<<<1, 128>>>(nb);
    scanC_kernel<<<nb, SCAN_BS>>>(N);
    scatter_kernel<<<(T + 255) / 256, 256>>>(T);
    gemm1_kernel<<<(N + GBM - 1) / GBM, 128>>>(x, W1, att_src1, att_dst1, N);
    gather1_kernel<<<((long long)N * 8 + 255) / 256, 256>>>(N);
    gemm2_kernel<<<(N + 255) / 256, 256>>>(W2, att_src2, att_dst2, b1, N);
    gather2_kernel<<<((long long)N * 4 + 255) / 256, 256>>>(N, b2, out);
}

// round 11
// speedup vs baseline: 2.2192x; 1.0723x over previous
#include <cuda_runtime.h>
#include <cuda_bf16.h>
#include <cuda_fp16.h>
#include <cstdint>

// Problem constants (fixed by setup_inputs)
#define MAXN 100000
#define MAXE 3200000
#define FIN  512
#define H1DIM 64   // 8 heads x 8 ch
#define HEADS 8
#define NCLS 16
#define MAXT (MAXE + MAXN)
#define SCAN_BS 1024
#define MAXB ((MAXN + SCAN_BS - 1) / SCAN_BS)

// ---------------- scratch (device globals; no allocations allowed) --------
__device__ __align__(16) __half g_h1h[MAXN * H1DIM];     // x @ W1 (fp16, gather src)
__device__ __align__(16) __half g_h2h[MAXN * NCLS];      // elu(out1+b1) @ W2 (fp16)
__device__ __align__(16) float  g_out1[MAXN * H1DIM];    // layer1 NORMALIZED agg
__device__ __align__(16) float2 g_as1e[MAXN * HEADS];    // {e^as, e^0.2as}
__device__ __align__(16) float2 g_ad1e[MAXN * HEADS];
__device__ __align__(16) float2 g_as2e[MAXN];
__device__ __align__(16) float2 g_ad2e[MAXN];
__device__ __align__(16) int g_src[MAXT];
__device__ __align__(16) int g_dst[MAXT];
__device__ __align__(16) int g_csr[MAXT];                // src sorted by dst
__device__ int g_deg[MAXN];
__device__ int g_off[MAXN];
__device__ int g_cursor[MAXN];
__device__ int g_bsum[MAXB + 1];
__device__ int g_bbase[MAXB + 1];
__device__ int g_is64;

__device__ __forceinline__ uint32_t sptr(const void* p) {
    return (uint32_t)__cvta_generic_to_shared(p);
}
__device__ __forceinline__ void ldsm4(uint32_t* r, uint32_t a) {
    asm volatile("ldmatrix.sync.aligned.m8n8.x4.shared.b16 {%0,%1,%2,%3}, [%4];"
        : "=r"(r[0]), "=r"(r[1]), "=r"(r[2]), "=r"(r[3]) : "r"(a));
}
__device__ __forceinline__ void ldsm4t(uint32_t* r, uint32_t a) {
    asm volatile("ldmatrix.sync.aligned.m8n8.x4.trans.shared.b16 {%0,%1,%2,%3}, [%4];"
        : "=r"(r[0]), "=r"(r[1]), "=r"(r[2]), "=r"(r[3]) : "r"(a));
}
__device__ __forceinline__ void mma_bf16(float* c, const uint32_t* a, const uint32_t* b) {
    asm volatile(
        "mma.sync.aligned.m16n8k16.row.col.f32.bf16.bf16.f32 "
        "{%0,%1,%2,%3}, {%4,%5,%6,%7}, {%8,%9}, {%0,%1,%2,%3};"
        : "+f"(c[0]), "+f"(c[1]), "+f"(c[2]), "+f"(c[3])
        : "r"(a[0]), "r"(a[1]), "r"(a[2]), "r"(a[3]), "r"(b[0]), "r"(b[1]));
}
__device__ __forceinline__ unsigned int b2u(__nv_bfloat16 a, __nv_bfloat16 b) {
    unsigned short ua = *(unsigned short*)&a, ub = *(unsigned short*)&b;
    return ((unsigned)ub << 16) | (unsigned)ua;
}
__device__ __forceinline__ float qreduce(float v) {   // sum over quad (lanes ^1, ^2)
    v += __shfl_xor_sync(0xFFFFFFFF, v, 1);
    v += __shfl_xor_sync(0xFFFFFFFF, v, 2);
    return v;
}

// ---------------- dtype detect: int64 edge_index has zero high words -------
__global__ void detect_kernel(const int* __restrict__ ei32) {
    unsigned ballot = __ballot_sync(0xFFFFFFFF, ei32[2 * threadIdx.x + 1] != 0);
    if (threadIdx.x == 0) g_is64 = (ballot == 0u) ? 1 : 0;
}

// ---------------- init: zero degree histogram ------------------------------
__global__ void init_kernel(int N) {
    int i = blockIdx.x * blockDim.x + threadIdx.x;
    if (i < N) g_deg[i] = 0;
}

// ---------------- convert edges + histogram over dst -----------------------
__global__ void convert_kernel(const void* __restrict__ ei, int E, int N) {
    int e = blockIdx.x * blockDim.x + threadIdx.x;
    int T = E + N;
    if (e >= T) return;
    int src, dst;
    if (e >= E) {
        src = dst = e - E;                  // self-loop
    } else if (g_is64) {
        const long long* p = (const long long*)ei;
        src = (int)p[e];
        dst = (int)p[(size_t)E + e];
    } else {
        const int* p = (const int*)ei;
        src = p[e];
        dst = p[E + e];
    }
    g_src[e] = src;
    g_dst[e] = dst;
    atomicAdd(&g_deg[dst], 1);
}

// ---------------- scan: block sums -> base scan -> per-block scan ----------
__global__ void scanA_kernel(int N) {
    __shared__ int s[SCAN_BS];
    int i = blockIdx.x * SCAN_BS + threadIdx.x;
    s[threadIdx.x] = (i < N) ? g_deg[i] : 0;
    __syncthreads();
    for (int o = SCAN_BS / 2; o > 0; o >>= 1) {
        if (threadIdx.x < o) s[threadIdx.x] += s[threadIdx.x + o];
        __syncthreads();
    }
    if (threadIdx.x == 0) g_bsum[blockIdx.x] = s[0];
}
__global__ void scanB_kernel(int nb) {   // nb <= 128
    __shared__ int s[128];
    int t = threadIdx.x;
    int v = (t < nb) ? g_bsum[t] : 0;
    s[t] = v;
    __syncthreads();
    for (int o = 1; o < 128; o <<= 1) {
        int u = (t >= o) ? s[t - o] : 0;
        __syncthreads();
        s[t] += u;
        __syncthreads();
    }
    if (t < nb) g_bbase[t] = s[t] - v;   // exclusive
}
__global__ void scanC_kernel(int N) {
    __shared__ int s[SCAN_BS];
    int tid = threadIdx.x;
    int i = blockIdx.x * SCAN_BS + tid;
    int v = (i < N) ? g_deg[i] : 0;
    s[tid] = v;
    __syncthreads();
    for (int o = 1; o < SCAN_BS; o <<= 1) {
        int t = (tid >= o) ? s[tid - o] : 0;
        __syncthreads();
        s[tid] += t;
        __syncthreads();
    }
    if (i < N) {
        int off = g_bbase[blockIdx.x] + s[tid] - v;   // exclusive prefix
        g_off[i] = off;
        g_cursor[i] = off;
    }
}

// ---------------- scatter edges into CSR by dst ----------------------------
__global__ void scatter_kernel(int T) {
    int e = blockIdx.x * blockDim.x + threadIdx.x;
    if (e >= T) return;
    int dst = g_dst[e];
    int slot = atomicAdd(&g_cursor[dst], 1);
    g_csr[slot] = g_src[e];
}
// after scatter: g_cursor[d] == g_off[d] + deg[d] == row end

// ---------------- GEMM1 (tensor core, split-bf16) + fused attn1 -----------
// 128 threads = 4 warps; warp w -> rows [w*32, w*32+32) x 64 cols.
// x = xh + xl (bf16); acc += xh*Wh + xl*Wh + xh*Wl
// Epilogue: fp16 h1 + per-head attention exp tables (fp32 dots).
#define GBM 128
#define ASTR 40     // A smem row stride (bf16)
#define BSTR 72     // B smem row stride (bf16)
__global__ __launch_bounds__(128) void gemm1_kernel(const float* __restrict__ x,
                                                    const float* __restrict__ W1,
                                                    const float* __restrict__ att_src,
                                                    const float* __restrict__ att_dst,
                                                    int M) {
    __shared__ __align__(16) __nv_bfloat16 Ah[GBM][ASTR];
    __shared__ __align__(16) __nv_bfloat16 Al[GBM][ASTR];
    __shared__ __align__(16) __nv_bfloat16 Bh[32][BSTR];   // [k][n]
    __shared__ __align__(16) __nv_bfloat16 Bl[32][BSTR];
    __shared__ float s_as[H1DIM], s_ad[H1DIM];
    int tid  = threadIdx.x;
    int lane = tid & 31;
    int wid  = tid >> 5;
    int m0   = blockIdx.x * GBM;
    int q    = lane & 3;
    int g    = lane >> 2;

    if (tid < H1DIM) { s_as[tid] = att_src[tid]; s_ad[tid] = att_dst[tid]; }

    float acc[2][8][4];
#pragma unroll
    for (int mt = 0; mt < 2; mt++)
#pragma unroll
        for (int nt = 0; nt < 8; nt++)
#pragma unroll
            for (int j = 0; j < 4; j++) acc[mt][nt][j] = 0.f;

    for (int k0 = 0; k0 < FIN; k0 += 32) {
        // --- A tile: 128 rows x 32 k; packed 8B smem stores
#pragma unroll
        for (int it = 0; it < 2; it++) {
#pragma unroll
            for (int pass = 0; pass < 4; pass++) {
                int row = pass * 32 + (tid >> 2);
                int c4  = (tid & 3) + it * 4;
                int gr  = m0 + row;
                float4 v = make_float4(0.f, 0.f, 0.f, 0.f);
                if (gr < M) v = *(const float4*)(x + (size_t)gr * FIN + k0 + c4 * 4);
                float vv[4] = {v.x, v.y, v.z, v.w};
                __nv_bfloat16 hb[4], lb[4];
#pragma unroll
                for (int j = 0; j < 4; j++) {
                    hb[j] = __float2bfloat16(vv[j]);
                    lb[j] = __float2bfloat16(vv[j] - __bfloat162float(hb[j]));
                }
                *(uint2*)&Ah[row][c4 * 4] = make_uint2(b2u(hb[0], hb[1]), b2u(hb[2], hb[3]));
                *(uint2*)&Al[row][c4 * 4] = make_uint2(b2u(lb[0], lb[1]), b2u(lb[2], lb[3]));
            }
        }
        // --- B tile: 32 k-rows x 64 n, natural [k][n]; packed 8B stores
#pragma unroll
        for (int p = 0; p < 4; p++) {
            int t  = tid + p * 128;
            int kr = t >> 4;       // 0..31
            int c4 = t & 15;
            float4 v = *(const float4*)(W1 + (size_t)(k0 + kr) * 64 + c4 * 4);
            float vv[4] = {v.x, v.y, v.z, v.w};
            __nv_bfloat16 hb[4], lb[4];
#pragma unroll
            for (int j = 0; j < 4; j++) {
                hb[j] = __float2bfloat16(vv[j]);
                lb[j] = __float2bfloat16(vv[j] - __bfloat162float(hb[j]));
            }
            *(uint2*)&Bh[kr][c4 * 4] = make_uint2(b2u(hb[0], hb[1]), b2u(hb[2], hb[3]));
            *(uint2*)&Bl[kr][c4 * 4] = make_uint2(b2u(lb[0], lb[1]), b2u(lb[2], lb[3]));
        }
        __syncthreads();

#pragma unroll
        for (int k16 = 0; k16 < 2; k16++) {
            int kkB = k16 * 16;
            uint32_t ah[2][4], al[2][4];
            int arow = lane & 15;
            int akk  = kkB + ((lane & 16) ? 8 : 0);
#pragma unroll
            for (int mt = 0; mt < 2; mt++) {
                ldsm4(ah[mt], sptr(&Ah[wid * 32 + mt * 16 + arow][akk]));
                ldsm4(al[mt], sptr(&Al[wid * 32 + mt * 16 + arow][akk]));
            }
#pragma unroll
            for (int p = 0; p < 4; p++) {
                int bk = kkB + (lane & 7) + ((lane & 8) ? 8 : 0);
                int bn = p * 16 + ((lane & 16) ? 8 : 0);
                uint32_t bh[4], bl[4];
                ldsm4t(bh, sptr(&Bh[bk][bn]));
                ldsm4t(bl, sptr(&Bl[bk][bn]));
#pragma unroll
                for (int mt = 0; mt < 2; mt++) {
                    mma_bf16(acc[mt][2 * p],     ah[mt], bh);
                    mma_bf16(acc[mt][2 * p],     al[mt], bh);
                    mma_bf16(acc[mt][2 * p],     ah[mt], bl);
                    mma_bf16(acc[mt][2 * p + 1], ah[mt], bh + 2);
                    mma_bf16(acc[mt][2 * p + 1], al[mt], bh + 2);
                    mma_bf16(acc[mt][2 * p + 1], ah[mt], bl + 2);
                }
            }
        }
        __syncthreads();
    }

    // --- epilogue: fp16 h1 + fused per-head attention exp tables
#pragma unroll
    for (int mt = 0; mt < 2; mt++) {
        int row0 = m0 + wid * 32 + mt * 16 + g;
        int row1 = row0 + 8;
#pragma unroll
        for (int nt = 0; nt < 8; nt++) {
            int col = nt * 8 + q * 2;
            if (row0 < M)
                *(__half2*)(g_h1h + (size_t)row0 * H1DIM + col) =
                    __floats2half2_rn(acc[mt][nt][0], acc[mt][nt][1]);
            if (row1 < M)
                *(__half2*)(g_h1h + (size_t)row1 * H1DIM + col) =
                    __floats2half2_rn(acc[mt][nt][2], acc[mt][nt][3]);
            // attention dots for head nt (cols nt*8..nt*8+7), fp32
            float sa0 = s_as[col], sa1 = s_as[col + 1];
            float sd0 = s_ad[col], sd1 = s_ad[col + 1];
            float pas0 = qreduce(acc[mt][nt][0] * sa0 + acc[mt][nt][1] * sa1);
            float pad0 = qreduce(acc[mt][nt][0] * sd0 + acc[mt][nt][1] * sd1);
            float pas1 = qreduce(acc[mt][nt][2] * sa0 + acc[mt][nt][3] * sa1);
            float pad1 = qreduce(acc[mt][nt][2] * sd0 + acc[mt][nt][3] * sd1);
            float v   = (q == 0) ? pas0 : (q == 1) ? pad0 : (q == 2) ? pas1 : pad1;
            int   row = (q < 2) ? row0 : row1;
            float2* tab = (q & 1) ? g_ad1e : g_as1e;
            if (row < M)
                tab[(size_t)row * HEADS + nt] = make_float2(__expf(v), __expf(0.2f * v));
        }
    }
}

// ---------------- layer 1 gather: agg + softmax (8 thr/dst, no atomics) ---
__global__ __launch_bounds__(256) void gather1_kernel(int N) {
    int gid = blockIdx.x * blockDim.x + threadIdx.x;
    int dst = gid >> 3;
    int h   = gid & 7;
    if (dst >= N) return;
    float2 da = g_ad1e[(size_t)dst * HEADS + h];
    int beg = g_off[dst];
    int end = g_cursor[dst];
    float4 a0 = make_float4(0.f, 0.f, 0.f, 0.f);
    float4 a1 = make_float4(0.f, 0.f, 0.f, 0.f);
    float denom = 0.f;
    for (int i = beg; i < end; i++) {
        int src = g_csr[i];
        float2 sa = g_as1e[(size_t)src * HEADS + h];
        float w = fmaxf(sa.x * da.x, sa.y * da.y);   // e^lrelu(as+ad)
        uint4 u = *(const uint4*)(g_h1h + (size_t)src * H1DIM + h * 8);  // 8 halves
        float2 p0 = __half22float2(*(__half2*)&u.x);
        float2 p1 = __half22float2(*(__half2*)&u.y);
        float2 p2 = __half22float2(*(__half2*)&u.z);
        float2 p3 = __half22float2(*(__half2*)&u.w);
        a0.x += w * p0.x; a0.y += w * p0.y; a0.z += w * p1.x; a0.w += w * p1.y;
        a1.x += w * p2.x; a1.y += w * p2.y; a1.z += w * p3.x; a1.w += w * p3.y;
        denom += w;
    }
    float inv = 1.f / denom;
    float* op = g_out1 + (size_t)dst * H1DIM + h * 8;
    *(float4*)op       = make_float4(a0.x * inv, a0.y * inv, a0.z * inv, a0.w * inv);
    *(float4*)(op + 4) = make_float4(a1.x * inv, a1.y * inv, a1.z * inv, a1.w * inv);
}

// ---------------- GEMM2: bias + elu fused; fp16 h2 + attn2 exp tables -----
__global__ __launch_bounds__(256) void gemm2_kernel(const float* __restrict__ W2,
                                                    const float* __restrict__ att_src2,
                                                    const float* __restrict__ att_dst2,
                                                    const float* __restrict__ b1, int N) {
    __shared__ float W2s[H1DIM * NCLS];
    __shared__ float s2[NCLS], d2[NCLS], b1s[H1DIM];
    int tid = threadIdx.x;
    for (int i = tid; i < H1DIM * NCLS; i += 256) W2s[i] = W2[i];
    if (tid < NCLS) { s2[tid] = att_src2[tid]; d2[tid] = att_dst2[tid]; }
    if (tid < H1DIM) b1s[tid] = b1[tid];
    __syncthreads();
    int n = blockIdx.x * blockDim.x + tid;
    if (n >= N) return;
    float acc[NCLS];
#pragma unroll
    for (int j = 0; j < NCLS; j++) acc[j] = 0.f;
    const float* row = g_out1 + (size_t)n * H1DIM;   // already normalized
#pragma unroll
    for (int c4 = 0; c4 < H1DIM / 4; c4++) {
        float4 v = *(const float4*)(row + c4 * 4);
        float vv[4] = {v.x, v.y, v.z, v.w};
#pragma unroll
        for (int u = 0; u < 4; u++) {
            int c = c4 * 4 + u;
            float val = vv[u] + b1s[c];
            val = val > 0.f ? val : (__expf(val) - 1.f);   // elu
#pragma unroll
            for (int j = 0; j < NCLS; j++) acc[j] += val * W2s[c * NCLS + j];
        }
    }
    float as = 0.f, ad = 0.f;
#pragma unroll
    for (int j = 0; j < NCLS; j++) { as += acc[j] * s2[j]; ad += acc[j] * d2[j]; }
    __half* hp = g_h2h + (size_t)n * NCLS;
#pragma unroll
    for (int j2 = 0; j2 < NCLS / 2; j2++)
        *(__half2*)(hp + j2 * 2) = __floats2half2_rn(acc[j2 * 2], acc[j2 * 2 + 1]);
    g_as2e[n] = make_float2(__expf(as), __expf(0.2f * as));
    g_ad2e[n] = make_float2(__expf(ad), __expf(0.2f * ad));
}

// ---------------- layer 2 gather: agg + softmax + bias (4 thr/dst) --------
__global__ __launch_bounds__(256) void gather2_kernel(int N, const float* __restrict__ b2,
                                                      float* __restrict__ out) {
    int gid = blockIdx.x * blockDim.x + threadIdx.x;
    int dst = gid >> 2;
    int t   = gid & 3;
    if (dst >= N) return;
    float2 da = g_ad2e[dst];
    float4 bv = *(const float4*)(b2 + t * 4);
    int beg = g_off[dst];
    int end = g_cursor[dst];
    float4 a = make_float4(0.f, 0.f, 0.f, 0.f);
    float denom = 0.f;
    for (int i = beg; i < end; i++) {
        int src = g_csr[i];
        float2 sa = g_as2e[src];
        float w = fmaxf(sa.x * da.x, sa.y * da.y);
        uint2 u = *(const uint2*)(g_h2h + (size_t)src * NCLS + t * 4);   // 4 halves
        float2 p0 = __half22float2(*(__half2*)&u.x);
        float2 p1 = __half22float2(*(__half2*)&u.y);
        a.x += w * p0.x; a.y += w * p0.y; a.z += w * p1.x; a.w += w * p1.y;
        denom += w;
    }
    float inv = 1.f / denom;
    *(float4*)(out + (size_t)dst * NCLS + t * 4) =
        make_float4(a.x * inv + bv.x, a.y * inv + bv.y,
                    a.z * inv + bv.z, a.w * inv + bv.w);
}

// ---------------------------------------------------------------------------
extern "C" void kernel_launch(void* const* d_in, const int* in_sizes, int n_in,
                              void* d_out, int out_size) {
    const float* x        = (const float*)d_in[0];
    const void*  ei       = d_in[1];
    const float* W1       = (const float*)d_in[2];
    const float* att_src1 = (const float*)d_in[3];
    const float* att_dst1 = (const float*)d_in[4];
    const float* b1       = (const float*)d_in[5];
    const float* W2       = (const float*)d_in[6];
    const float* att_src2 = (const float*)d_in[7];
    const float* att_dst2 = (const float*)d_in[8];
    const float* b2       = (const float*)d_in[9];
    float* out = (float*)d_out;

    int N = in_sizes[0] / FIN;       // 100000
    int E = in_sizes[1] / 2;         // 3200000
    int T = E + N;
    int nb = (N + SCAN_BS - 1) / SCAN_BS;

    detect_kernel<<<1, 32>>>((const int*)ei);
    init_kernel<<<(N + 255) / 256, 256>>>(N);
    convert_kernel<<<(T + 255) / 256, 256>>>(ei, E, N);
    scanA_kernel<<<nb, SCAN_BS>>>(N);
    scanB_kernel<<<1, 128>>>(nb);
    scanC_kernel<<<nb, SCAN_BS>>>(N);
    scatter_kernel<<<(T + 255) / 256, 256>>>(T);
    gemm1_kernel<<<(N + GBM - 1) / GBM, 128>>>(x, W1, att_src1, att_dst1, N);
    gather1_kernel<<<((long long)N * 8 + 255) / 256, 256>>>(N);
    gemm2_kernel<<<(N + 255) / 256, 256>>>(W2, att_src2, att_dst2, b1, N);
    gather2_kernel<<<((long long)N * 4 + 255) / 256, 256>>>(N, b2, out);
}

// round 14
// speedup vs baseline: 2.3352x; 1.0523x over previous
#include <cuda_runtime.h>
#include <cuda_bf16.h>
#include <cuda_fp16.h>
#include <cstdint>

// Problem constants (fixed by setup_inputs)
#define MAXN 100000
#define MAXE 3200000
#define FIN  512
#define H1DIM 64   // 8 heads x 8 ch
#define HEADS 8
#define NCLS 16
#define MAXT (MAXE + MAXN)
#define SCAN_BS 1024
#define MAXB ((MAXN + SCAN_BS - 1) / SCAN_BS)

// ---------------- scratch (device globals; no allocations allowed) --------
__device__ __align__(16) __half g_h1h[MAXN * H1DIM];     // x @ W1 (fp16, gather src)
__device__ __align__(16) __half g_h2h[MAXN * NCLS];      // elu(out1+b1) @ W2 (fp16)
__device__ __align__(16) float  g_out1[MAXN * H1DIM];    // layer1 NORMALIZED agg
__device__ __align__(16) float2 g_as1e[MAXN * HEADS];    // {e^as, e^0.2as}
__device__ __align__(16) float2 g_ad1e[MAXN * HEADS];
__device__ __align__(16) float2 g_as2e[MAXN];
__device__ __align__(16) float2 g_ad2e[MAXN];
__device__ __align__(16) int g_csr[MAXT];                // src sorted by dst
__device__ int g_deg[MAXN];
__device__ int g_off[MAXN];
__device__ int g_cursor[MAXN];
__device__ int g_bsum[MAXB + 1];
__device__ int g_bbase[MAXB + 1];
__device__ int g_is64;

__device__ __forceinline__ uint32_t sptr(const void* p) {
    return (uint32_t)__cvta_generic_to_shared(p);
}
__device__ __forceinline__ void ldsm4(uint32_t* r, uint32_t a) {
    asm volatile("ldmatrix.sync.aligned.m8n8.x4.shared.b16 {%0,%1,%2,%3}, [%4];"
        : "=r"(r[0]), "=r"(r[1]), "=r"(r[2]), "=r"(r[3]) : "r"(a));
}
__device__ __forceinline__ void ldsm4t(uint32_t* r, uint32_t a) {
    asm volatile("ldmatrix.sync.aligned.m8n8.x4.trans.shared.b16 {%0,%1,%2,%3}, [%4];"
        : "=r"(r[0]), "=r"(r[1]), "=r"(r[2]), "=r"(r[3]) : "r"(a));
}
__device__ __forceinline__ void mma_bf16(float* c, const uint32_t* a, const uint32_t* b) {
    asm volatile(
        "mma.sync.aligned.m16n8k16.row.col.f32.bf16.bf16.f32 "
        "{%0,%1,%2,%3}, {%4,%5,%6,%7}, {%8,%9}, {%0,%1,%2,%3};"
        : "+f"(c[0]), "+f"(c[1]), "+f"(c[2]), "+f"(c[3])
        : "r"(a[0]), "r"(a[1]), "r"(a[2]), "r"(a[3]), "r"(b[0]), "r"(b[1]));
}
__device__ __forceinline__ unsigned int b2u(__nv_bfloat16 a, __nv_bfloat16 b) {
    unsigned short ua = *(unsigned short*)&a, ub = *(unsigned short*)&b;
    return ((unsigned)ub << 16) | (unsigned)ua;
}
__device__ __forceinline__ float qreduce(float v) {   // sum over quad (lanes ^1, ^2)
    v += __shfl_xor_sync(0xFFFFFFFF, v, 1);
    v += __shfl_xor_sync(0xFFFFFFFF, v, 2);
    return v;
}

// decode edge e (0..T-1): src/dst with self-loops appended
__device__ __forceinline__ int edge_dst(const void* ei, int e, int E) {
    if (e >= E) return e - E;
    return g_is64 ? (int)((const long long*)ei)[(size_t)E + e]
                  : ((const int*)ei)[E + e];
}
__device__ __forceinline__ int edge_src(const void* ei, int e, int E) {
    if (e >= E) return e - E;
    return g_is64 ? (int)((const long long*)ei)[e]
                  : ((const int*)ei)[e];
}

// ---------------- dtype detect: int64 edge_index has zero high words -------
__global__ void detect_kernel(const int* __restrict__ ei32) {
    unsigned ballot = __ballot_sync(0xFFFFFFFF, ei32[2 * threadIdx.x + 1] != 0);
    if (threadIdx.x == 0) g_is64 = (ballot == 0u) ? 1 : 0;
}

// ---------------- init: zero degree histogram ------------------------------
__global__ void init_kernel(int N) {
    int i = blockIdx.x * blockDim.x + threadIdx.x;
    if (i < N) g_deg[i] = 0;
}

// ---------------- histogram over dst (reads edge_index directly) ----------
__global__ void hist_kernel(const void* __restrict__ ei, int E, int N) {
    int e = blockIdx.x * blockDim.x + threadIdx.x;
    if (e >= E + N) return;
    atomicAdd(&g_deg[edge_dst(ei, e, E)], 1);
}

// ---------------- scan: block sums -> base scan -> per-block scan ----------
__global__ void scanA_kernel(int N) {
    __shared__ int s[SCAN_BS];
    int i = blockIdx.x * SCAN_BS + threadIdx.x;
    s[threadIdx.x] = (i < N) ? g_deg[i] : 0;
    __syncthreads();
    for (int o = SCAN_BS / 2; o > 0; o >>= 1) {
        if (threadIdx.x < o) s[threadIdx.x] += s[threadIdx.x + o];
        __syncthreads();
    }
    if (threadIdx.x == 0) g_bsum[blockIdx.x] = s[0];
}
__global__ void scanB_kernel(int nb) {   // nb <= 128
    __shared__ int s[128];
    int t = threadIdx.x;
    int v = (t < nb) ? g_bsum[t] : 0;
    s[t] = v;
    __syncthreads();
    for (int o = 1; o < 128; o <<= 1) {
        int u = (t >= o) ? s[t - o] : 0;
        __syncthreads();
        s[t] += u;
        __syncthreads();
    }
    if (t < nb) g_bbase[t] = s[t] - v;   // exclusive
}
__global__ void scanC_kernel(int N) {
    __shared__ int s[SCAN_BS];
    int tid = threadIdx.x;
    int i = blockIdx.x * SCAN_BS + tid;
    int v = (i < N) ? g_deg[i] : 0;
    s[tid] = v;
    __syncthreads();
    for (int o = 1; o < SCAN_BS; o <<= 1) {
        int t = (tid >= o) ? s[tid - o] : 0;
        __syncthreads();
        s[tid] += t;
        __syncthreads();
    }
    if (i < N) {
        int off = g_bbase[blockIdx.x] + s[tid] - v;   // exclusive prefix
        g_off[i] = off;
        g_cursor[i] = off;
    }
}

// ---------------- scatter edges into CSR by dst (reads edge_index) --------
__global__ void scatter_kernel(const void* __restrict__ ei, int E, int N) {
    int e = blockIdx.x * blockDim.x + threadIdx.x;
    if (e >= E + N) return;
    int dst = edge_dst(ei, e, E);
    int slot = atomicAdd(&g_cursor[dst], 1);
    g_csr[slot] = edge_src(ei, e, E);
}
// after scatter: g_cursor[d] == g_off[d] + deg[d] == row end

// ---------------- GEMM1 (tensor core, split-bf16, sw-pipelined) -----------
// 128 threads = 4 warps; warp w -> rows [w*32, w*32+32) x 64 cols.
// x = xh + xl (bf16); acc += xh*Wh + xl*Wh + xh*Wl
// Global->reg prefetch of next k-chunk overlaps with mma of current chunk.
#define GBM 128
#define ASTR 40     // A smem row stride (bf16)
#define BSTR 72     // B smem row stride (bf16)

__device__ __forceinline__ void g1_load_a(const float* __restrict__ x, int m0, int M,
                                          int k0, int tid, float4* ra) {
#pragma unroll
    for (int it = 0; it < 2; it++)
#pragma unroll
        for (int pass = 0; pass < 4; pass++) {
            int row = pass * 32 + (tid >> 2);
            int c4  = (tid & 3) + it * 4;
            int gr  = m0 + row;
            float4 v = make_float4(0.f, 0.f, 0.f, 0.f);
            if (gr < M) v = *(const float4*)(x + (size_t)gr * FIN + k0 + c4 * 4);
            ra[it * 4 + pass] = v;
        }
}
__device__ __forceinline__ void g1_load_b(const float* __restrict__ W1, int k0,
                                          int tid, float4* rb) {
#pragma unroll
    for (int p = 0; p < 4; p++) {
        int t  = tid + p * 128;
        int kr = t >> 4;
        int c4 = t & 15;
        rb[p] = *(const float4*)(W1 + (size_t)(k0 + kr) * 64 + c4 * 4);
    }
}

__global__ __launch_bounds__(128) void gemm1_kernel(const float* __restrict__ x,
                                                    const float* __restrict__ W1,
                                                    const float* __restrict__ att_src,
                                                    const float* __restrict__ att_dst,
                                                    int M) {
    __shared__ __align__(16) __nv_bfloat16 Ah[GBM][ASTR];
    __shared__ __align__(16) __nv_bfloat16 Al[GBM][ASTR];
    __shared__ __align__(16) __nv_bfloat16 Bh[32][BSTR];   // [k][n]
    __shared__ __align__(16) __nv_bfloat16 Bl[32][BSTR];
    __shared__ float s_as[H1DIM], s_ad[H1DIM];
    int tid  = threadIdx.x;
    int lane = tid & 31;
    int wid  = tid >> 5;
    int m0   = blockIdx.x * GBM;
    int q    = lane & 3;
    int g    = lane >> 2;

    if (tid < H1DIM) { s_as[tid] = att_src[tid]; s_ad[tid] = att_dst[tid]; }

    float acc[2][8][4];
#pragma unroll
    for (int mt = 0; mt < 2; mt++)
#pragma unroll
        for (int nt = 0; nt < 8; nt++)
#pragma unroll
            for (int j = 0; j < 4; j++) acc[mt][nt][j] = 0.f;

    float4 ra[8], rb[4];
    g1_load_a(x, m0, M, 0, tid, ra);
    g1_load_b(W1, 0, tid, rb);

    for (int k0 = 0; k0 < FIN; k0 += 32) {
        // --- convert + store current chunk regs -> smem (hi/lo split)
#pragma unroll
        for (int it = 0; it < 2; it++)
#pragma unroll
            for (int pass = 0; pass < 4; pass++) {
                int row = pass * 32 + (tid >> 2);
                int c4  = (tid & 3) + it * 4;
                float4 v = ra[it * 4 + pass];
                float vv[4] = {v.x, v.y, v.z, v.w};
                __nv_bfloat16 hb[4], lb[4];
#pragma unroll
                for (int j = 0; j < 4; j++) {
                    hb[j] = __float2bfloat16(vv[j]);
                    lb[j] = __float2bfloat16(vv[j] - __bfloat162float(hb[j]));
                }
                *(uint2*)&Ah[row][c4 * 4] = make_uint2(b2u(hb[0], hb[1]), b2u(hb[2], hb[3]));
                *(uint2*)&Al[row][c4 * 4] = make_uint2(b2u(lb[0], lb[1]), b2u(lb[2], lb[3]));
            }
#pragma unroll
        for (int p = 0; p < 4; p++) {
            int t  = tid + p * 128;
            int kr = t >> 4;
            int c4 = t & 15;
            float4 v = rb[p];
            float vv[4] = {v.x, v.y, v.z, v.w};
            __nv_bfloat16 hb[4], lb[4];
#pragma unroll
            for (int j = 0; j < 4; j++) {
                hb[j] = __float2bfloat16(vv[j]);
                lb[j] = __float2bfloat16(vv[j] - __bfloat162float(hb[j]));
            }
            *(uint2*)&Bh[kr][c4 * 4] = make_uint2(b2u(hb[0], hb[1]), b2u(hb[2], hb[3]));
            *(uint2*)&Bl[kr][c4 * 4] = make_uint2(b2u(lb[0], lb[1]), b2u(lb[2], lb[3]));
        }
        __syncthreads();

        // --- prefetch next chunk into regs (latency hidden under mma below)
        if (k0 + 32 < FIN) {
            g1_load_a(x, m0, M, k0 + 32, tid, ra);
            g1_load_b(W1, k0 + 32, tid, rb);
        }

        // --- mma from smem
#pragma unroll
        for (int k16 = 0; k16 < 2; k16++) {
            int kkB = k16 * 16;
            uint32_t ah[2][4], al[2][4];
            int arow = lane & 15;
            int akk  = kkB + ((lane & 16) ? 8 : 0);
#pragma unroll
            for (int mt = 0; mt < 2; mt++) {
                ldsm4(ah[mt], sptr(&Ah[wid * 32 + mt * 16 + arow][akk]));
                ldsm4(al[mt], sptr(&Al[wid * 32 + mt * 16 + arow][akk]));
            }
#pragma unroll
            for (int p = 0; p < 4; p++) {
                int bk = kkB + (lane & 7) + ((lane & 8) ? 8 : 0);
                int bn = p * 16 + ((lane & 16) ? 8 : 0);
                uint32_t bh[4], bl[4];
                ldsm4t(bh, sptr(&Bh[bk][bn]));
                ldsm4t(bl, sptr(&Bl[bk][bn]));
#pragma unroll
                for (int mt = 0; mt < 2; mt++) {
                    mma_bf16(acc[mt][2 * p],     ah[mt], bh);
                    mma_bf16(acc[mt][2 * p],     al[mt], bh);
                    mma_bf16(acc[mt][2 * p],     ah[mt], bl);
                    mma_bf16(acc[mt][2 * p + 1], ah[mt], bh + 2);
                    mma_bf16(acc[mt][2 * p + 1], al[mt], bh + 2);
                    mma_bf16(acc[mt][2 * p + 1], ah[mt], bl + 2);
                }
            }
        }
        __syncthreads();
    }

    // --- epilogue: fp16 h1 + fused per-head attention exp tables
#pragma unroll
    for (int mt = 0; mt < 2; mt++) {
        int row0 = m0 + wid * 32 + mt * 16 + g;
        int row1 = row0 + 8;
#pragma unroll
        for (int nt = 0; nt < 8; nt++) {
            int col = nt * 8 + q * 2;
            if (row0 < M)
                *(__half2*)(g_h1h + (size_t)row0 * H1DIM + col) =
                    __floats2half2_rn(acc[mt][nt][0], acc[mt][nt][1]);
            if (row1 < M)
                *(__half2*)(g_h1h + (size_t)row1 * H1DIM + col) =
                    __floats2half2_rn(acc[mt][nt][2], acc[mt][nt][3]);
            // attention dots for head nt (cols nt*8..nt*8+7), fp32
            float sa0 = s_as[col], sa1 = s_as[col + 1];
            float sd0 = s_ad[col], sd1 = s_ad[col + 1];
            float pas0 = qreduce(acc[mt][nt][0] * sa0 + acc[mt][nt][1] * sa1);
            float pad0 = qreduce(acc[mt][nt][0] * sd0 + acc[mt][nt][1] * sd1);
            float pas1 = qreduce(acc[mt][nt][2] * sa0 + acc[mt][nt][3] * sa1);
            float pad1 = qreduce(acc[mt][nt][2] * sd0 + acc[mt][nt][3] * sd1);
            float v   = (q == 0) ? pas0 : (q == 1) ? pad0 : (q == 2) ? pas1 : pad1;
            int   row = (q < 2) ? row0 : row1;
            float2* tab = (q & 1) ? g_ad1e : g_as1e;
            if (row < M)
                tab[(size_t)row * HEADS + nt] = make_float2(__expf(v), __expf(0.2f * v));
        }
    }
}

// ---------------- layer 1 gather: agg + softmax (8 thr/dst, no atomics) ---
__global__ __launch_bounds__(256) void gather1_kernel(int N) {
    int gid = blockIdx.x * blockDim.x + threadIdx.x;
    int dst = gid >> 3;
    int h   = gid & 7;
    if (dst >= N) return;
    float2 da = g_ad1e[(size_t)dst * HEADS + h];
    int beg = g_off[dst];
    int end = g_cursor[dst];
    float4 a0 = make_float4(0.f, 0.f, 0.f, 0.f);
    float4 a1 = make_float4(0.f, 0.f, 0.f, 0.f);
    float denom = 0.f;
    for (int i = beg; i < end; i++) {
        int src = g_csr[i];
        float2 sa = g_as1e[(size_t)src * HEADS + h];
        float w = fmaxf(sa.x * da.x, sa.y * da.y);   // e^lrelu(as+ad)
        uint4 u = *(const uint4*)(g_h1h + (size_t)src * H1DIM + h * 8);  // 8 halves
        float2 p0 = __half22float2(*(__half2*)&u.x);
        float2 p1 = __half22float2(*(__half2*)&u.y);
        float2 p2 = __half22float2(*(__half2*)&u.z);
        float2 p3 = __half22float2(*(__half2*)&u.w);
        a0.x += w * p0.x; a0.y += w * p0.y; a0.z += w * p1.x; a0.w += w * p1.y;
        a1.x += w * p2.x; a1.y += w * p2.y; a1.z += w * p3.x; a1.w += w * p3.y;
        denom += w;
    }
    float inv = 1.f / denom;
    float* op = g_out1 + (size_t)dst * H1DIM + h * 8;
    *(float4*)op       = make_float4(a0.x * inv, a0.y * inv, a0.z * inv, a0.w * inv);
    *(float4*)(op + 4) = make_float4(a1.x * inv, a1.y * inv, a1.z * inv, a1.w * inv);
}

// ---------------- GEMM2: bias + elu fused; fp16 h2 + attn2 exp tables -----
__global__ __launch_bounds__(256) void gemm2_kernel(const float* __restrict__ W2,
                                                    const float* __restrict__ att_src2,
                                                    const float* __restrict__ att_dst2,
                                                    const float* __restrict__ b1, int N) {
    __shared__ float W2s[H1DIM * NCLS];
    __shared__ float s2[NCLS], d2[NCLS], b1s[H1DIM];
    int tid = threadIdx.x;
    for (int i = tid; i < H1DIM * NCLS; i += 256) W2s[i] = W2[i];
    if (tid < NCLS) { s2[tid] = att_src2[tid]; d2[tid] = att_dst2[tid]; }
    if (tid < H1DIM) b1s[tid] = b1[tid];
    __syncthreads();
    int n = blockIdx.x * blockDim.x + tid;
    if (n >= N) return;
    float acc[NCLS];
#pragma unroll
    for (int j = 0; j < NCLS; j++) acc[j] = 0.f;
    const float* row = g_out1 + (size_t)n * H1DIM;   // already normalized
#pragma unroll
    for (int c4 = 0; c4 < H1DIM / 4; c4++) {
        float4 v = *(const float4*)(row + c4 * 4);
        float vv[4] = {v.x, v.y, v.z, v.w};
#pragma unroll
        for (int u = 0; u < 4; u++) {
            int c = c4 * 4 + u;
            float val = vv[u] + b1s[c];
            val = val > 0.f ? val : (__expf(val) - 1.f);   // elu
#pragma unroll
            for (int j = 0; j < NCLS; j++) acc[j] += val * W2s[c * NCLS + j];
        }
    }
    float as = 0.f, ad = 0.f;
#pragma unroll
    for (int j = 0; j < NCLS; j++) { as += acc[j] * s2[j]; ad += acc[j] * d2[j]; }
    __half* hp = g_h2h + (size_t)n * NCLS;
#pragma unroll
    for (int j2 = 0; j2 < NCLS / 2; j2++)
        *(__half2*)(hp + j2 * 2) = __floats2half2_rn(acc[j2 * 2], acc[j2 * 2 + 1]);
    g_as2e[n] = make_float2(__expf(as), __expf(0.2f * as));
    g_ad2e[n] = make_float2(__expf(ad), __expf(0.2f * ad));
}

// ---------------- layer 2 gather: agg + softmax + bias (4 thr/dst) --------
__global__ __launch_bounds__(256) void gather2_kernel(int N, const float* __restrict__ b2,
                                                      float* __restrict__ out) {
    int gid = blockIdx.x * blockDim.x + threadIdx.x;
    int dst = gid >> 2;
    int t   = gid & 3;
    if (dst >= N) return;
    float2 da = g_ad2e[dst];
    float4 bv = *(const float4*)(b2 + t * 4);
    int beg = g_off[dst];
    int end = g_cursor[dst];
    float4 a = make_float4(0.f, 0.f, 0.f, 0.f);
    float denom = 0.f;
    for (int i = beg; i < end; i++) {
        int src = g_csr[i];
        float2 sa = g_as2e[src];
        float w = fmaxf(sa.x * da.x, sa.y * da.y);
        uint2 u = *(const uint2*)(g_h2h + (size_t)src * NCLS + t * 4);   // 4 halves
        float2 p0 = __half22float2(*(__half2*)&u.x);
        float2 p1 = __half22float2(*(__half2*)&u.y);
        a.x += w * p0.x; a.y += w * p0.y; a.z += w * p1.x; a.w += w * p1.y;
        denom += w;
    }
    float inv = 1.f / denom;
    *(float4*)(out + (size_t)dst * NCLS + t * 4) =
        make_float4(a.x * inv + bv.x, a.y * inv + bv.y,
                    a.z * inv + bv.z, a.w * inv + bv.w);
}

// ---------------------------------------------------------------------------
extern "C" void kernel_launch(void* const* d_in, const int* in_sizes, int n_in,
                              void* d_out, int out_size) {
    const float* x        = (const float*)d_in[0];
    const void*  ei       = d_in[1];
    const float* W1       = (const float*)d_in[2];
    const float* att_src1 = (const float*)d_in[3];
    const float* att_dst1 = (const float*)d_in[4];
    const float* b1       = (const float*)d_in[5];
    const float* W2       = (const float*)d_in[6];
    const float* att_src2 = (const float*)d_in[7];
    const float* att_dst2 = (const float*)d_in[8];
    const float* b2       = (const float*)d_in[9];
    float* out = (float*)d_out;

    int N = in_sizes[0] / FIN;       // 100000
    int E = in_sizes[1] / 2;         // 3200000
    int T = E + N;
    int nb = (N + SCAN_BS - 1) / SCAN_BS;

    detect_kernel<<<1, 32>>>((const int*)ei);
    init_kernel<<<(N + 255) / 256, 256>>>(N);
    hist_kernel<<<(T + 255) / 256, 256>>>(ei, E, N);
    scanA_kernel<<<nb, SCAN_BS>>>(N);
    scanB_kernel<<<1, 128>>>(nb);
    scanC_kernel<<<nb, SCAN_BS>>>(N);
    scatter_kernel<<<(T + 255) / 256, 256>>>(ei, E, N);
    gemm1_kernel<<<(N + GBM - 1) / GBM, 128>>>(x, W1, att_src1, att_dst1, N);
    gather1_kernel<<<((long long)N * 8 + 255) / 256, 256>>>(N);
    gemm2_kernel<<<(N + 255) / 256, 256>>>(W2, att_src2, att_dst2, b1, N);
    gather2_kernel<<<((long long)N * 4 + 255) / 256, 256>>>(N, b2, out);
}

// round 15
// speedup vs baseline: 2.3920x; 1.0243x over previous
#include <cuda_runtime.h>
#include <cuda_bf16.h>
#include <cuda_fp16.h>
#include <cstdint>

// Problem constants (fixed by setup_inputs)
#define MAXN 100000
#define MAXE 3200000
#define FIN  512
#define H1DIM 64   // 8 heads x 8 ch
#define HEADS 8
#define NCLS 16
#define MAXT (MAXE + MAXN)
#define SCAN_BS 1024
#define MAXB ((MAXN + SCAN_BS - 1) / SCAN_BS)

// ---------------- scratch (device globals; no allocations allowed) --------
__device__ __align__(16) __half  g_h1h[MAXN * H1DIM];    // x @ W1 (fp16, gather src)
__device__ __align__(16) __half  g_h2h[MAXN * NCLS];     // elu(out1+b1) @ W2 (fp16)
__device__ __align__(16) float   g_out1[MAXN * H1DIM];   // layer1 NORMALIZED agg
__device__ __align__(16) __half2 g_as1e[MAXN * HEADS];   // {e^as, e^0.2as} fp16
__device__ __align__(16) __half2 g_ad1e[MAXN * HEADS];
__device__ __align__(16) __half2 g_as2e[MAXN];
__device__ __align__(16) __half2 g_ad2e[MAXN];
__device__ __align__(16) int g_csr[MAXT];                // src sorted by dst
__device__ int g_deg[MAXN];
__device__ int g_off[MAXN];
__device__ int g_cursor[MAXN];
__device__ int g_bsum[MAXB + 1];
__device__ int g_bbase[MAXB + 1];
__device__ int g_is64;

__device__ __forceinline__ uint32_t sptr(const void* p) {
    return (uint32_t)__cvta_generic_to_shared(p);
}
__device__ __forceinline__ void ldsm4(uint32_t* r, uint32_t a) {
    asm volatile("ldmatrix.sync.aligned.m8n8.x4.shared.b16 {%0,%1,%2,%3}, [%4];"
        : "=r"(r[0]), "=r"(r[1]), "=r"(r[2]), "=r"(r[3]) : "r"(a));
}
__device__ __forceinline__ void ldsm4t(uint32_t* r, uint32_t a) {
    asm volatile("ldmatrix.sync.aligned.m8n8.x4.trans.shared.b16 {%0,%1,%2,%3}, [%4];"
        : "=r"(r[0]), "=r"(r[1]), "=r"(r[2]), "=r"(r[3]) : "r"(a));
}
__device__ __forceinline__ void mma_bf16(float* c, const uint32_t* a, const uint32_t* b) {
    asm volatile(
        "mma.sync.aligned.m16n8k16.row.col.f32.bf16.bf16.f32 "
        "{%0,%1,%2,%3}, {%4,%5,%6,%7}, {%8,%9}, {%0,%1,%2,%3};"
        : "+f"(c[0]), "+f"(c[1]), "+f"(c[2]), "+f"(c[3])
        : "r"(a[0]), "r"(a[1]), "r"(a[2]), "r"(a[3]), "r"(b[0]), "r"(b[1]));
}
__device__ __forceinline__ unsigned int b2u(__nv_bfloat16 a, __nv_bfloat16 b) {
    unsigned short ua = *(unsigned short*)&a, ub = *(unsigned short*)&b;
    return ((unsigned)ub << 16) | (unsigned)ua;
}
__device__ __forceinline__ float qreduce(float v) {   // sum over quad (lanes ^1, ^2)
    v += __shfl_xor_sync(0xFFFFFFFF, v, 1);
    v += __shfl_xor_sync(0xFFFFFFFF, v, 2);
    return v;
}

// decode edge e (0..T-1): src/dst with self-loops appended
__device__ __forceinline__ int edge_dst(const void* ei, int e, int E) {
    if (e >= E) return e - E;
    return g_is64 ? (int)((const long long*)ei)[(size_t)E + e]
                  : ((const int*)ei)[E + e];
}
__device__ __forceinline__ int edge_src(const void* ei, int e, int E) {
    if (e >= E) return e - E;
    return g_is64 ? (int)((const long long*)ei)[e]
                  : ((const int*)ei)[e];
}

// ---------------- setup: dtype detect (block 0) + zero degree histogram ----
__global__ void setup_kernel(const int* __restrict__ ei32, int N) {
    if (blockIdx.x == 0 && threadIdx.x < 32) {
        unsigned ballot = __ballot_sync(0xFFFFFFFF, ei32[2 * threadIdx.x + 1] != 0);
        if (threadIdx.x == 0) g_is64 = (ballot == 0u) ? 1 : 0;
    }
    int i = blockIdx.x * blockDim.x + threadIdx.x;
    if (i < N) g_deg[i] = 0;
}

// ---------------- histogram over dst (reads edge_index directly) ----------
__global__ void hist_kernel(const void* __restrict__ ei, int E, int N) {
    int e = blockIdx.x * blockDim.x + threadIdx.x;
    if (e >= E + N) return;
    atomicAdd(&g_deg[edge_dst(ei, e, E)], 1);
}

// ---------------- scan: block sums -> base scan -> per-block scan ----------
__global__ void scanA_kernel(int N) {
    __shared__ int s[SCAN_BS];
    int i = blockIdx.x * SCAN_BS + threadIdx.x;
    s[threadIdx.x] = (i < N) ? g_deg[i] : 0;
    __syncthreads();
    for (int o = SCAN_BS / 2; o > 0; o >>= 1) {
        if (threadIdx.x < o) s[threadIdx.x] += s[threadIdx.x + o];
        __syncthreads();
    }
    if (threadIdx.x == 0) g_bsum[blockIdx.x] = s[0];
}
__global__ void scanB_kernel(int nb) {   // nb <= 128
    __shared__ int s[128];
    int t = threadIdx.x;
    int v = (t < nb) ? g_bsum[t] : 0;
    s[t] = v;
    __syncthreads();
    for (int o = 1; o < 128; o <<= 1) {
        int u = (t >= o) ? s[t - o] : 0;
        __syncthreads();
        s[t] += u;
        __syncthreads();
    }
    if (t < nb) g_bbase[t] = s[t] - v;   // exclusive
}
__global__ void scanC_kernel(int N) {
    __shared__ int s[SCAN_BS];
    int tid = threadIdx.x;
    int i = blockIdx.x * SCAN_BS + tid;
    int v = (i < N) ? g_deg[i] : 0;
    s[tid] = v;
    __syncthreads();
    for (int o = 1; o < SCAN_BS; o <<= 1) {
        int t = (tid >= o) ? s[tid - o] : 0;
        __syncthreads();
        s[tid] += t;
        __syncthreads();
    }
    if (i < N) {
        int off = g_bbase[blockIdx.x] + s[tid] - v;   // exclusive prefix
        g_off[i] = off;
        g_cursor[i] = off;
    }
}

// ---------------- scatter edges into CSR by dst (reads edge_index) --------
__global__ void scatter_kernel(const void* __restrict__ ei, int E, int N) {
    int e = blockIdx.x * blockDim.x + threadIdx.x;
    if (e >= E + N) return;
    int dst = edge_dst(ei, e, E);
    int slot = atomicAdd(&g_cursor[dst], 1);
    g_csr[slot] = edge_src(ei, e, E);
}
// after scatter: g_cursor[d] == g_off[d] + deg[d] == row end

// ---------------- GEMM1 (tensor core, split-bf16, sw-pipelined) -----------
#define GBM 128
#define ASTR 40     // A smem row stride (bf16)
#define BSTR 72     // B smem row stride (bf16)

__device__ __forceinline__ void g1_load_a(const float* __restrict__ x, int m0, int M,
                                          int k0, int tid, float4* ra) {
#pragma unroll
    for (int it = 0; it < 2; it++)
#pragma unroll
        for (int pass = 0; pass < 4; pass++) {
            int row = pass * 32 + (tid >> 2);
            int c4  = (tid & 3) + it * 4;
            int gr  = m0 + row;
            float4 v = make_float4(0.f, 0.f, 0.f, 0.f);
            if (gr < M) v = *(const float4*)(x + (size_t)gr * FIN + k0 + c4 * 4);
            ra[it * 4 + pass] = v;
        }
}
__device__ __forceinline__ void g1_load_b(const float* __restrict__ W1, int k0,
                                          int tid, float4* rb) {
#pragma unroll
    for (int p = 0; p < 4; p++) {
        int t  = tid + p * 128;
        int kr = t >> 4;
        int c4 = t & 15;
        rb[p] = *(const float4*)(W1 + (size_t)(k0 + kr) * 64 + c4 * 4);
    }
}

__global__ __launch_bounds__(128) void gemm1_kernel(const float* __restrict__ x,
                                                    const float* __restrict__ W1,
                                                    const float* __restrict__ att_src,
                                                    const float* __restrict__ att_dst,
                                                    int M) {
    __shared__ __align__(16) __nv_bfloat16 Ah[GBM][ASTR];
    __shared__ __align__(16) __nv_bfloat16 Al[GBM][ASTR];
    __shared__ __align__(16) __nv_bfloat16 Bh[32][BSTR];   // [k][n]
    __shared__ __align__(16) __nv_bfloat16 Bl[32][BSTR];
    __shared__ float s_as[H1DIM], s_ad[H1DIM];
    int tid  = threadIdx.x;
    int lane = tid & 31;
    int wid  = tid >> 5;
    int m0   = blockIdx.x * GBM;
    int q    = lane & 3;
    int g    = lane >> 2;

    if (tid < H1DIM) { s_as[tid] = att_src[tid]; s_ad[tid] = att_dst[tid]; }

    float acc[2][8][4];
#pragma unroll
    for (int mt = 0; mt < 2; mt++)
#pragma unroll
        for (int nt = 0; nt < 8; nt++)
#pragma unroll
            for (int j = 0; j < 4; j++) acc[mt][nt][j] = 0.f;

    float4 ra[8], rb[4];
    g1_load_a(x, m0, M, 0, tid, ra);
    g1_load_b(W1, 0, tid, rb);

    for (int k0 = 0; k0 < FIN; k0 += 32) {
        // --- convert + store current chunk regs -> smem (hi/lo split)
#pragma unroll
        for (int it = 0; it < 2; it++)
#pragma unroll
            for (int pass = 0; pass < 4; pass++) {
                int row = pass * 32 + (tid >> 2);
                int c4  = (tid & 3) + it * 4;
                float4 v = ra[it * 4 + pass];
                float vv[4] = {v.x, v.y, v.z, v.w};
                __nv_bfloat16 hb[4], lb[4];
#pragma unroll
                for (int j = 0; j < 4; j++) {
                    hb[j] = __float2bfloat16(vv[j]);
                    lb[j] = __float2bfloat16(vv[j] - __bfloat162float(hb[j]));
                }
                *(uint2*)&Ah[row][c4 * 4] = make_uint2(b2u(hb[0], hb[1]), b2u(hb[2], hb[3]));
                *(uint2*)&Al[row][c4 * 4] = make_uint2(b2u(lb[0], lb[1]), b2u(lb[2], lb[3]));
            }
#pragma unroll
        for (int p = 0; p < 4; p++) {
            int t  = tid + p * 128;
            int kr = t >> 4;
            int c4 = t & 15;
            float4 v = rb[p];
            float vv[4] = {v.x, v.y, v.z, v.w};
            __nv_bfloat16 hb[4], lb[4];
#pragma unroll
            for (int j = 0; j < 4; j++) {
                hb[j] = __float2bfloat16(vv[j]);
                lb[j] = __float2bfloat16(vv[j] - __bfloat162float(hb[j]));
            }
            *(uint2*)&Bh[kr][c4 * 4] = make_uint2(b2u(hb[0], hb[1]), b2u(hb[2], hb[3]));
            *(uint2*)&Bl[kr][c4 * 4] = make_uint2(b2u(lb[0], lb[1]), b2u(lb[2], lb[3]));
        }
        __syncthreads();

        // --- prefetch next chunk into regs (latency hidden under mma below)
        if (k0 + 32 < FIN) {
            g1_load_a(x, m0, M, k0 + 32, tid, ra);
            g1_load_b(W1, k0 + 32, tid, rb);
        }

        // --- mma from smem
#pragma unroll
        for (int k16 = 0; k16 < 2; k16++) {
            int kkB = k16 * 16;
            uint32_t ah[2][4], al[2][4];
            int arow = lane & 15;
            int akk  = kkB + ((lane & 16) ? 8 : 0);
#pragma unroll
            for (int mt = 0; mt < 2; mt++) {
                ldsm4(ah[mt], sptr(&Ah[wid * 32 + mt * 16 + arow][akk]));
                ldsm4(al[mt], sptr(&Al[wid * 32 + mt * 16 + arow][akk]));
            }
#pragma unroll
            for (int p = 0; p < 4; p++) {
                int bk = kkB + (lane & 7) + ((lane & 8) ? 8 : 0);
                int bn = p * 16 + ((lane & 16) ? 8 : 0);
                uint32_t bh[4], bl[4];
                ldsm4t(bh, sptr(&Bh[bk][bn]));
                ldsm4t(bl, sptr(&Bl[bk][bn]));
#pragma unroll
                for (int mt = 0; mt < 2; mt++) {
                    mma_bf16(acc[mt][2 * p],     ah[mt], bh);
                    mma_bf16(acc[mt][2 * p],     al[mt], bh);
                    mma_bf16(acc[mt][2 * p],     ah[mt], bl);
                    mma_bf16(acc[mt][2 * p + 1], ah[mt], bh + 2);
                    mma_bf16(acc[mt][2 * p + 1], al[mt], bh + 2);
                    mma_bf16(acc[mt][2 * p + 1], ah[mt], bl + 2);
                }
            }
        }
        __syncthreads();
    }

    // --- epilogue: fp16 h1 + fused per-head attention exp tables (fp16)
#pragma unroll
    for (int mt = 0; mt < 2; mt++) {
        int row0 = m0 + wid * 32 + mt * 16 + g;
        int row1 = row0 + 8;
#pragma unroll
        for (int nt = 0; nt < 8; nt++) {
            int col = nt * 8 + q * 2;
            if (row0 < M)
                *(__half2*)(g_h1h + (size_t)row0 * H1DIM + col) =
                    __floats2half2_rn(acc[mt][nt][0], acc[mt][nt][1]);
            if (row1 < M)
                *(__half2*)(g_h1h + (size_t)row1 * H1DIM + col) =
                    __floats2half2_rn(acc[mt][nt][2], acc[mt][nt][3]);
            // attention dots for head nt (cols nt*8..nt*8+7), fp32
            float sa0 = s_as[col], sa1 = s_as[col + 1];
            float sd0 = s_ad[col], sd1 = s_ad[col + 1];
            float pas0 = qreduce(acc[mt][nt][0] * sa0 + acc[mt][nt][1] * sa1);
            float pad0 = qreduce(acc[mt][nt][0] * sd0 + acc[mt][nt][1] * sd1);
            float pas1 = qreduce(acc[mt][nt][2] * sa0 + acc[mt][nt][3] * sa1);
            float pad1 = qreduce(acc[mt][nt][2] * sd0 + acc[mt][nt][3] * sd1);
            float v   = (q == 0) ? pas0 : (q == 1) ? pad0 : (q == 2) ? pas1 : pad1;
            int   row = (q < 2) ? row0 : row1;
            __half2* tab = (q & 1) ? g_ad1e : g_as1e;
            if (row < M)
                tab[(size_t)row * HEADS + nt] = __floats2half2_rn(__expf(v), __expf(0.2f * v));
        }
    }
}

// ---------------- layer 1 gather: agg + softmax (8 thr/dst, prefetched) ---
__global__ __launch_bounds__(256) void gather1_kernel(int N) {
    int gid = blockIdx.x * blockDim.x + threadIdx.x;
    int dst = gid >> 3;
    int h   = gid & 7;
    if (dst >= N) return;
    float2 da = __half22float2(g_ad1e[(size_t)dst * HEADS + h]);
    int beg = g_off[dst];
    int end = g_cursor[dst];
    float4 a0 = make_float4(0.f, 0.f, 0.f, 0.f);
    float4 a1 = make_float4(0.f, 0.f, 0.f, 0.f);
    float denom = 0.f;
    // software pipeline: current edge's operands preloaded
    int src = g_csr[beg];
    __half2 sah = g_as1e[(size_t)src * HEADS + h];
    uint4 u = *(const uint4*)(g_h1h + (size_t)src * H1DIM + h * 8);
    for (int i = beg; i < end; i++) {
        int nsrc = (i + 1 < end) ? g_csr[i + 1] : src;
        __half2 nsah = g_as1e[(size_t)nsrc * HEADS + h];
        uint4 nu = *(const uint4*)(g_h1h + (size_t)nsrc * H1DIM + h * 8);
        float2 sa = __half22float2(sah);
        float w = fmaxf(sa.x * da.x, sa.y * da.y);   // e^lrelu(as+ad)
        float2 p0 = __half22float2(*(__half2*)&u.x);
        float2 p1 = __half22float2(*(__half2*)&u.y);
        float2 p2 = __half22float2(*(__half2*)&u.z);
        float2 p3 = __half22float2(*(__half2*)&u.w);
        a0.x += w * p0.x; a0.y += w * p0.y; a0.z += w * p1.x; a0.w += w * p1.y;
        a1.x += w * p2.x; a1.y += w * p2.y; a1.z += w * p3.x; a1.w += w * p3.y;
        denom += w;
        sah = nsah; u = nu; src = nsrc;
    }
    float inv = 1.f / denom;
    float* op = g_out1 + (size_t)dst * H1DIM + h * 8;
    *(float4*)op       = make_float4(a0.x * inv, a0.y * inv, a0.z * inv, a0.w * inv);
    *(float4*)(op + 4) = make_float4(a1.x * inv, a1.y * inv, a1.z * inv, a1.w * inv);
}

// ---------------- GEMM2: bias + elu fused; fp16 h2 + attn2 exp tables -----
__global__ __launch_bounds__(256) void gemm2_kernel(const float* __restrict__ W2,
                                                    const float* __restrict__ att_src2,
                                                    const float* __restrict__ att_dst2,
                                                    const float* __restrict__ b1, int N) {
    __shared__ float W2s[H1DIM * NCLS];
    __shared__ float s2[NCLS], d2[NCLS], b1s[H1DIM];
    int tid = threadIdx.x;
    for (int i = tid; i < H1DIM * NCLS; i += 256) W2s[i] = W2[i];
    if (tid < NCLS) { s2[tid] = att_src2[tid]; d2[tid] = att_dst2[tid]; }
    if (tid < H1DIM) b1s[tid] = b1[tid];
    __syncthreads();
    int n = blockIdx.x * blockDim.x + tid;
    if (n >= N) return;
    float acc[NCLS];
#pragma unroll
    for (int j = 0; j < NCLS; j++) acc[j] = 0.f;
    const float* row = g_out1 + (size_t)n * H1DIM;   // already normalized
#pragma unroll
    for (int c4 = 0; c4 < H1DIM / 4; c4++) {
        float4 v = *(const float4*)(row + c4 * 4);
        float vv[4] = {v.x, v.y, v.z, v.w};
#pragma unroll
        for (int u = 0; u < 4; u++) {
            int c = c4 * 4 + u;
            float val = vv[u] + b1s[c];
            val = val > 0.f ? val : (__expf(val) - 1.f);   // elu
#pragma unroll
            for (int j = 0; j < NCLS; j++) acc[j] += val * W2s[c * NCLS + j];
        }
    }
    float as = 0.f, ad = 0.f;
#pragma unroll
    for (int j = 0; j < NCLS; j++) { as += acc[j] * s2[j]; ad += acc[j] * d2[j]; }
    __half* hp = g_h2h + (size_t)n * NCLS;
#pragma unroll
    for (int j2 = 0; j2 < NCLS / 2; j2++)
        *(__half2*)(hp + j2 * 2) = __floats2half2_rn(acc[j2 * 2], acc[j2 * 2 + 1]);
    g_as2e[n] = __floats2half2_rn(__expf(as), __expf(0.2f * as));
    g_ad2e[n] = __floats2half2_rn(__expf(ad), __expf(0.2f * ad));
}

// ---------------- layer 2 gather: agg + softmax + bias (4 thr/dst) --------
__global__ __launch_bounds__(256) void gather2_kernel(int N, const float* __restrict__ b2,
                                                      float* __restrict__ out) {
    int gid = blockIdx.x * blockDim.x + threadIdx.x;
    int dst = gid >> 2;
    int t   = gid & 3;
    if (dst >= N) return;
    float2 da = __half22float2(g_ad2e[dst]);
    float4 bv = *(const float4*)(b2 + t * 4);
    int beg = g_off[dst];
    int end = g_cursor[dst];
    float4 a = make_float4(0.f, 0.f, 0.f, 0.f);
    float denom = 0.f;
    int src = g_csr[beg];
    __half2 sah = g_as2e[src];
    uint2 u = *(const uint2*)(g_h2h + (size_t)src * NCLS + t * 4);
    for (int i = beg; i < end; i++) {
        int nsrc = (i + 1 < end) ? g_csr[i + 1] : src;
        __half2 nsah = g_as2e[nsrc];
        uint2 nu = *(const uint2*)(g_h2h + (size_t)nsrc * NCLS + t * 4);
        float2 sa = __half22float2(sah);
        float w = fmaxf(sa.x * da.x, sa.y * da.y);
        float2 p0 = __half22float2(*(__half2*)&u.x);
        float2 p1 = __half22float2(*(__half2*)&u.y);
        a.x += w * p0.x; a.y += w * p0.y; a.z += w * p1.x; a.w += w * p1.y;
        denom += w;
        sah = nsah; u = nu; src = nsrc;
    }
    float inv = 1.f / denom;
    *(float4*)(out + (size_t)dst * NCLS + t * 4) =
        make_float4(a.x * inv + bv.x, a.y * inv + bv.y,
                    a.z * inv + bv.z, a.w * inv + bv.w);
}

// ---------------------------------------------------------------------------
extern "C" void kernel_launch(void* const* d_in, const int* in_sizes, int n_in,
                              void* d_out, int out_size) {
    const float* x        = (const float*)d_in[0];
    const void*  ei       = d_in[1];
    const float* W1       = (const float*)d_in[2];
    const float* att_src1 = (const float*)d_in[3];
    const float* att_dst1 = (const float*)d_in[4];
    const float* b1       = (const float*)d_in[5];
    const float* W2       = (const float*)d_in[6];
    const float* att_src2 = (const float*)d_in[7];
    const float* att_dst2 = (const float*)d_in[8];
    const float* b2       = (const float*)d_in[9];
    float* out = (float*)d_out;

    int N = in_sizes[0] / FIN;       // 100000
    int E = in_sizes[1] / 2;         // 3200000
    int T = E + N;
    int nb = (N + SCAN_BS - 1) / SCAN_BS;

    setup_kernel<<<(N + 255) / 256, 256>>>((const int*)ei, N);
    hist_kernel<<<(T + 255) / 256, 256>>>(ei, E, N);
    scanA_kernel<<<nb, SCAN_BS>>>(N);
    scanB_kernel<<<1, 128>>>(nb);
    scanC_kernel<<<nb, SCAN_BS>>>(N);
    scatter_kernel<<<(T + 255) / 256, 256>>>(ei, E, N);
    gemm1_kernel<<<(N + GBM - 1) / GBM, 128>>>(x, W1, att_src1, att_dst1, N);
    gather1_kernel<<<((long long)N * 8 + 255) / 256, 256>>>(N);
    gemm2_kernel<<<(N + 255) / 256, 256>>>(W2, att_src2, att_dst2, b1, N);
    gather2_kernel<<<((long long)N * 4 + 255) / 256, 256>>>(N, b2, out);
}